// round 7
// baseline (speedup 1.0000x reference)
#include <cuda_runtime.h>
#include <cuda_fp16.h>
#include <math.h>
#include <stdint.h>

// ---------------------------------------------------------------------------
// Problem constants
// ---------------------------------------------------------------------------
#define B_   64
#define P_   225
#define K_   16
#define D_   640
#define MQ   (B_ * P_)      // 14400 query rows
#define NR   (K_ * P_)      // 3600 reference rows
#define NRP  3648           // NR padded to 57*64
#define NT_  57             // n tiles of 64

// GEMM tiling
#define BM 64
#define BN 64
#define BK 64
#define LDA 648             // A smem row stride (fp16 elems), pad for banks
#define LDB 72              // B smem row stride
#define NSTRIPE 4

#define A_SMEM_BYTES (BM * LDA * 2)                 // 82944
#define B_SMEM_BYTES (2 * BN * LDB * 2)             // 18432
#define RED_OFF      (A_SMEM_BYTES + B_SMEM_BYTES)  // 101376
#define SMEM_BYTES   (RED_OFF + BM * 5 * 4)         // 102656

// ---------------------------------------------------------------------------
// Scratch (allocation-free: __device__ globals)
// ---------------------------------------------------------------------------
__device__ __half g_qh[MQ * D_];            // raw q_patch in fp16
__device__ __half g_rh[NRP * D_];           // normalized r_patch fp16 (pad 0)
__device__ float g_qnorm[MQ];               // ||q_patch row||
__device__ float g_pmax[NSTRIPE * MQ];      // per-stripe max of q.rn
__device__ float g_h1p[5][K_ * 160];        // adapter partials
__device__ float g_h1[K_ * 160];            // adapter hidden
__device__ float g_famean[D_];              // mean adapter output

// ---------------------------------------------------------------------------
// Kernel 1: q prep — convert to fp16 (raw), compute row norms. float4 I/O.
// ---------------------------------------------------------------------------
__global__ void prep_q_kernel(const float* __restrict__ in) {
    const int row = blockIdx.x;
    const float4* x4 = (const float4*)(in + (size_t)row * D_);
    __half* o = g_qh + (size_t)row * D_;
    float ss = 0.f;
    for (int i4 = threadIdx.x; i4 < D_ / 4; i4 += 128) {
        float4 v = x4[i4];
        ss = fmaf(v.x, v.x, ss);
        ss = fmaf(v.y, v.y, ss);
        ss = fmaf(v.z, v.z, ss);
        ss = fmaf(v.w, v.w, ss);
        *(__half2*)(o + i4 * 4)     = __floats2half2_rn(v.x, v.y);
        *(__half2*)(o + i4 * 4 + 2) = __floats2half2_rn(v.z, v.w);
    }
    #pragma unroll
    for (int of = 16; of > 0; of >>= 1) ss += __shfl_xor_sync(0xffffffffu, ss, of);
    __shared__ float wsum[4];
    if ((threadIdx.x & 31) == 0) wsum[threadIdx.x >> 5] = ss;
    __syncthreads();
    if (threadIdx.x == 0)
        g_qnorm[row] = sqrtf(wsum[0] + wsum[1] + wsum[2] + wsum[3]);
}

// ---------------------------------------------------------------------------
// Kernel 2: r prep — L2 normalize, convert to fp16; zero-fill pad rows
// ---------------------------------------------------------------------------
__global__ void prep_r_kernel(const float* __restrict__ in) {
    const int row = blockIdx.x;
    __half* o = g_rh + (size_t)row * D_;
    if (row >= NR) {
        for (int i = threadIdx.x; i < D_ / 2; i += 128)
            *(__half2*)(o + i * 2) = __floats2half2_rn(0.f, 0.f);
        return;
    }
    const float4* x4 = (const float4*)(in + (size_t)row * D_);
    float ss = 0.f;
    for (int i4 = threadIdx.x; i4 < D_ / 4; i4 += 128) {
        float4 v = x4[i4];
        ss = fmaf(v.x, v.x, ss);
        ss = fmaf(v.y, v.y, ss);
        ss = fmaf(v.z, v.z, ss);
        ss = fmaf(v.w, v.w, ss);
    }
    #pragma unroll
    for (int of = 16; of > 0; of >>= 1) ss += __shfl_xor_sync(0xffffffffu, ss, of);
    __shared__ float wsum[4];
    if ((threadIdx.x & 31) == 0) wsum[threadIdx.x >> 5] = ss;
    __syncthreads();
    const float scale = 1.f / (sqrtf(wsum[0] + wsum[1] + wsum[2] + wsum[3]) + 1e-6f);
    for (int i4 = threadIdx.x; i4 < D_ / 4; i4 += 128) {
        float4 v = x4[i4];
        *(__half2*)(o + i4 * 4)     = __floats2half2_rn(v.x * scale, v.y * scale);
        *(__half2*)(o + i4 * 4 + 2) = __floats2half2_rn(v.z * scale, v.w * scale);
    }
}

// ---------------------------------------------------------------------------
// mma.sync fp16 m16n8k16, f16 accumulate (2 packed regs)
// ---------------------------------------------------------------------------
__device__ __forceinline__ void mma16816h(uint32_t c[2], const uint32_t a[4],
                                          const uint32_t b[2]) {
    asm volatile(
        "mma.sync.aligned.m16n8k16.row.col.f16.f16.f16.f16 "
        "{%0,%1}, {%2,%3,%4,%5}, {%6,%7}, {%0,%1};\n"
        : "+r"(c[0]), "+r"(c[1])
        : "r"(a[0]), "r"(a[1]), "r"(a[2]), "r"(a[3]), "r"(b[0]), "r"(b[1]));
}

// ---------------------------------------------------------------------------
// Kernel 3: tensor-core GEMM + row max.
// grid (225, 4): block = 64 q rows, n-stripe = tiles {q, q+4, ...} of BN=64.
// A (64 x 640 fp16) resident in smem; B double-buffered BK=64 stages.
// f16 accumulate within each BK chunk, drained to fp32 per chunk.
// ---------------------------------------------------------------------------
__global__ __launch_bounds__(256, 2)
void gemm_max_kernel() {
    extern __shared__ __align__(16) char smem[];
    __half* As = (__half*)smem;
    __half* Bs = (__half*)(smem + A_SMEM_BYTES);
    float* red = (float*)(smem + RED_OFF);

    const int tid  = threadIdx.x;
    const int lane = tid & 31;
    const int g    = lane >> 2;     // group id 0..7
    const int tig  = lane & 3;      // thread-in-group 0..3
    const int w    = tid >> 5;
    const int wy   = w >> 2;        // 0..1 (m)
    const int wx   = w & 3;         // 0..3 (n)
    const int rowBase = blockIdx.x * BM;

    // ---- load full-K A tile: 64 x 640 fp16, uint4 (8 elem) chunks ----
    {
        const __half* gq = g_qh + (size_t)rowBase * D_;
        #pragma unroll
        for (int i = 0; i < 20; ++i) {
            int idx = tid + i * 256;
            int row = idx / 80, kg = idx % 80;
            *(uint4*)(As + row * LDA + kg * 8) =
                *(const uint4*)(gq + (size_t)row * D_ + kg * 8);
        }
    }
    __syncthreads();

    float rm[2][2] = {{-1e30f, -1e30f}, {-1e30f, -1e30f}};  // [mtile][row g / g+8]

    const int n0 = tid >> 3, kg0 = tid & 7;                   // B ldg/sts idx0
    const int n1 = (tid + 256) >> 3, kg1 = kg0;               // idx1

    for (int nt = blockIdx.y; nt < NT_; nt += NSTRIPE) {
        const int nBase = nt * BN;
        float acc[2][2][4];
        #pragma unroll
        for (int i = 0; i < 2; ++i)
            #pragma unroll
            for (int j = 0; j < 2; ++j)
                #pragma unroll
                for (int r = 0; r < 4; ++r) acc[i][j][r] = 0.f;

        const __half* gB = g_rh + (size_t)nBase * D_;

        // prologue: stage 0
        {
            uint4 v0 = *(const uint4*)(gB + (size_t)n0 * D_ + kg0 * 8);
            uint4 v1 = *(const uint4*)(gB + (size_t)n1 * D_ + kg1 * 8);
            *(uint4*)(Bs + n0 * LDB + kg0 * 8) = v0;
            *(uint4*)(Bs + n1 * LDB + kg1 * 8) = v1;
        }
        __syncthreads();

        for (int kt = 0; kt < 10; ++kt) {
            uint4 v0, v1;
            if (kt < 9) {
                v0 = *(const uint4*)(gB + (size_t)n0 * D_ + (kt + 1) * BK + kg0 * 8);
                v1 = *(const uint4*)(gB + (size_t)n1 * D_ + (kt + 1) * BK + kg1 * 8);
            }
            const __half* bufC = Bs + (kt & 1) * BN * LDB;
            const int kA0 = kt * BK;

            // f16 accumulators for this K-chunk
            uint32_t hacc[2][2][2];
            #pragma unroll
            for (int i = 0; i < 2; ++i)
                #pragma unroll
                for (int j = 0; j < 2; ++j) {
                    hacc[i][j][0] = 0u;
                    hacc[i][j][1] = 0u;
                }

            #pragma unroll
            for (int ks = 0; ks < 4; ++ks) {
                const int kA = kA0 + ks * 16;
                uint32_t a[2][4], b[2][2];
                #pragma unroll
                for (int i = 0; i < 2; ++i) {
                    const __half* base =
                        As + (wy * 32 + i * 16 + g) * LDA + kA + tig * 2;
                    a[i][0] = *(const uint32_t*)(base);
                    a[i][1] = *(const uint32_t*)(base + 8 * LDA);
                    a[i][2] = *(const uint32_t*)(base + 8);
                    a[i][3] = *(const uint32_t*)(base + 8 * LDA + 8);
                }
                #pragma unroll
                for (int j = 0; j < 2; ++j) {
                    const __half* base =
                        bufC + (wx * 16 + j * 8 + g) * LDB + ks * 16 + tig * 2;
                    b[j][0] = *(const uint32_t*)(base);
                    b[j][1] = *(const uint32_t*)(base + 8);
                }
                #pragma unroll
                for (int i = 0; i < 2; ++i)
                    #pragma unroll
                    for (int j = 0; j < 2; ++j)
                        mma16816h(hacc[i][j], a[i], b[j]);
            }

            // drain chunk f16 accumulators into fp32
            #pragma unroll
            for (int i = 0; i < 2; ++i)
                #pragma unroll
                for (int j = 0; j < 2; ++j) {
                    float2 f0 = __half22float2(*(__half2*)&hacc[i][j][0]);
                    float2 f1 = __half22float2(*(__half2*)&hacc[i][j][1]);
                    acc[i][j][0] += f0.x;
                    acc[i][j][1] += f0.y;
                    acc[i][j][2] += f1.x;
                    acc[i][j][3] += f1.y;
                }

            if (kt < 9) {
                __half* bufN = Bs + ((kt + 1) & 1) * BN * LDB;
                *(uint4*)(bufN + n0 * LDB + kg0 * 8) = v0;
                *(uint4*)(bufN + n1 * LDB + kg1 * 8) = v1;
                __syncthreads();
            }
        }

        // fold masked max of this n-tile into running max
        #pragma unroll
        for (int j = 0; j < 2; ++j) {
            const int c0 = nBase + wx * 16 + j * 8 + tig * 2;
            const bool v0 = (c0 < NR), v1 = (c0 + 1 < NR);
            #pragma unroll
            for (int i = 0; i < 2; ++i) {
                if (v0) {
                    rm[i][0] = fmaxf(rm[i][0], acc[i][j][0]);
                    rm[i][1] = fmaxf(rm[i][1], acc[i][j][2]);
                }
                if (v1) {
                    rm[i][0] = fmaxf(rm[i][0], acc[i][j][1]);
                    rm[i][1] = fmaxf(rm[i][1], acc[i][j][3]);
                }
            }
        }
        __syncthreads();   // before reusing Bs buffers in next tile's prologue
    }

    // ---- reduce across tig lanes, then across wx warps via smem ----
    #pragma unroll
    for (int i = 0; i < 2; ++i)
        #pragma unroll
        for (int s = 0; s < 2; ++s) {
            float v = rm[i][s];
            v = fmaxf(v, __shfl_xor_sync(0xffffffffu, v, 1));
            v = fmaxf(v, __shfl_xor_sync(0xffffffffu, v, 2));
            rm[i][s] = v;
        }
    if (tig == 0) {
        #pragma unroll
        for (int i = 0; i < 2; ++i)
            #pragma unroll
            for (int s = 0; s < 2; ++s) {
                int row = wy * 32 + i * 16 + s * 8 + g;
                red[row * 5 + wx] = rm[i][s];
            }
    }
    __syncthreads();
    if (tid < BM) {
        float m = red[tid * 5 + 0];
        m = fmaxf(m, red[tid * 5 + 1]);
        m = fmaxf(m, red[tid * 5 + 2]);
        m = fmaxf(m, red[tid * 5 + 3]);
        g_pmax[blockIdx.y * MQ + rowBase + tid] = m;
    }
}

// ---------------------------------------------------------------------------
// Kernel 4a: adapter partials — grid (16 k, 5 dchunk) x 160 threads
// ---------------------------------------------------------------------------
__global__ void adapter_h1_part(const float* __restrict__ r_img,
                                const float* __restrict__ w1) {
    const int k = blockIdx.x, dc = blockIdx.y, i = threadIdx.x;
    __shared__ float xr[128];
    if (i < 128) xr[i] = r_img[k * D_ + dc * 128 + i];
    __syncthreads();
    float s0 = 0.f, s1 = 0.f;
    const float* w = w1 + (size_t)(dc * 128) * 160 + i;
    #pragma unroll 8
    for (int d = 0; d < 128; d += 2) {
        s0 = fmaf(xr[d], w[(size_t)d * 160], s0);
        s1 = fmaf(xr[d + 1], w[(size_t)(d + 1) * 160], s1);
    }
    g_h1p[dc][k * 160 + i] = s0 + s1;
}

// ---------------------------------------------------------------------------
// Kernel 4b: combine partials + relu
// ---------------------------------------------------------------------------
__global__ void adapter_h1_comb() {
    const int idx = blockIdx.x * 256 + threadIdx.x;
    if (idx < K_ * 160) {
        float s = g_h1p[0][idx] + g_h1p[1][idx] + g_h1p[2][idx] +
                  g_h1p[3][idx] + g_h1p[4][idx];
        g_h1[idx] = fmaxf(s, 0.f);
    }
}

// ---------------------------------------------------------------------------
// Kernel 4c: famean[j] = mean_k relu(h1[k] @ w2[:,j]); grid=5 x 128
// ---------------------------------------------------------------------------
__global__ void adapter_out_kernel(const float* __restrict__ w2) {
    __shared__ float h1s[K_ * 160];
    for (int idx = threadIdx.x; idx < K_ * 160; idx += 128) h1s[idx] = g_h1[idx];
    __syncthreads();
    const int j = blockIdx.x * 128 + threadIdx.x;
    float accm = 0.f;
    for (int k = 0; k < K_; ++k) {
        float s0 = 0.f, s1 = 0.f;
        const float* h = h1s + k * 160;
        #pragma unroll 4
        for (int i = 0; i < 160; i += 2) {
            s0 = fmaf(h[i], w2[i * D_ + j], s0);
            s1 = fmaf(h[i + 1], w2[(i + 1) * D_ + j], s1);
        }
        accm += fmaxf(s0 + s1, 0.f);
    }
    g_famean[j] = accm * (1.f / (float)K_);
}

// ---------------------------------------------------------------------------
// Kernel 5: both heads + final score; one block per batch element.
// Computes amap from partial maxes + q norms here.
// ---------------------------------------------------------------------------
__global__ void heads_kernel(
    const float* __restrict__ q_img,
    const float* __restrict__ dh_w1, const float* __restrict__ dh_b1,
    const float* __restrict__ dh_g2, const float* __restrict__ dh_be2,
    const float* __restrict__ dh_w2, const float* __restrict__ dh_b2,
    const float* __restrict__ dh_g3, const float* __restrict__ dh_be3,
    const float* __restrict__ dh_w3, const float* __restrict__ dh_b3,
    const float* __restrict__ dr_w1, const float* __restrict__ dr_b1,
    const float* __restrict__ dr_g2, const float* __restrict__ dr_be2,
    const float* __restrict__ dr_w2, const float* __restrict__ dr_b2,
    const float* __restrict__ dr_g3, const float* __restrict__ dr_be3,
    const float* __restrict__ dr_w3, const float* __restrict__ dr_b3,
    float* __restrict__ out) {
    const int b = blockIdx.x;
    const int t = threadIdx.x;          // 128 threads
    __shared__ float xr[D_];
    __shared__ float am[P_];
    __shared__ float h1[128];
    __shared__ float h2[64];
    __shared__ float s_ref_s, s_map_s, mean_s;

    for (int i = t; i < D_; i += 128) xr[i] = q_img[b * D_ + i] - g_famean[i];
    for (int i = t; i < P_; i += 128) {
        const int r = b * P_ + i;
        float mx = g_pmax[r];
        mx = fmaxf(mx, g_pmax[MQ + r]);
        mx = fmaxf(mx, g_pmax[2 * MQ + r]);
        mx = fmaxf(mx, g_pmax[3 * MQ + r]);
        am[i] = 0.5f * (1.f - mx / (g_qnorm[r] + 1e-6f));
    }
    __syncthreads();

    // ---- dr head on xr (640 -> 128 -> 64 -> 1) ----
    {
        float s = dr_b1[t];
        for (int d = 0; d < D_; ++d) s = fmaf(xr[d], dr_w1[d * 128 + t], s);
        h1[t] = fmaxf(s, 0.f) * dr_g2[t] + dr_be2[t];
    }
    __syncthreads();
    if (t < 64) {
        float s = dr_b2[t];
        for (int i = 0; i < 128; ++i) s = fmaf(h1[i], dr_w2[i * 64 + t], s);
        h2[t] = fmaxf(s, 0.f) * dr_g3[t] + dr_be3[t];
    }
    __syncthreads();
    if (t == 0) {
        float s = dr_b3[0];
        for (int i = 0; i < 64; ++i) s = fmaf(h2[i], dr_w3[i], s);
        s_ref_s = 1.f / (1.f + expf(-s));
    }
    __syncthreads();

    // ---- dh head on am (225 -> 128 -> 64 -> 1) ----
    {
        float s = dh_b1[t];
        for (int p = 0; p < P_; ++p) s = fmaf(am[p], dh_w1[p * 128 + t], s);
        h1[t] = fmaxf(s, 0.f) * dh_g2[t] + dh_be2[t];
    }
    __syncthreads();
    if (t < 64) {
        float s = dh_b2[t];
        for (int i = 0; i < 128; ++i) s = fmaf(h1[i], dh_w2[i * 64 + t], s);
        h2[t] = fmaxf(s, 0.f) * dh_g3[t] + dh_be3[t];
    }
    __syncthreads();
    if (t == 0) {
        float s = dh_b3[0];
        for (int i = 0; i < 64; ++i) s = fmaf(h2[i], dh_w3[i], s);
        s_map_s = 1.f / (1.f + expf(-s));
        float msum = 0.f;
        for (int p = 0; p < P_; ++p) msum += am[p];
        mean_s = msum / (float)P_;
        out[b] = 0.5f * (s_ref_s + s_map_s) + mean_s;
    }
}

// ---------------------------------------------------------------------------
// Launch
// ---------------------------------------------------------------------------
extern "C" void kernel_launch(void* const* d_in, const int* in_sizes, int n_in,
                              void* d_out, int out_size) {
    const float* q_patch = (const float*)d_in[0];
    const float* r_patch = (const float*)d_in[1];
    const float* q_img   = (const float*)d_in[2];
    const float* r_img   = (const float*)d_in[3];
    const float* adpt_w1 = (const float*)d_in[4];
    const float* adpt_w2 = (const float*)d_in[5];
    const float* dh_w1  = (const float*)d_in[6];
    const float* dh_b1  = (const float*)d_in[7];
    const float* dh_g2  = (const float*)d_in[8];
    const float* dh_be2 = (const float*)d_in[9];
    const float* dh_w2  = (const float*)d_in[10];
    const float* dh_b2  = (const float*)d_in[11];
    const float* dh_g3  = (const float*)d_in[12];
    const float* dh_be3 = (const float*)d_in[13];
    const float* dh_w3  = (const float*)d_in[14];
    const float* dh_b3  = (const float*)d_in[15];
    const float* dr_w1  = (const float*)d_in[16];
    const float* dr_b1  = (const float*)d_in[17];
    const float* dr_g2  = (const float*)d_in[18];
    const float* dr_be2 = (const float*)d_in[19];
    const float* dr_w2  = (const float*)d_in[20];
    const float* dr_b2  = (const float*)d_in[21];
    const float* dr_g3  = (const float*)d_in[22];
    const float* dr_be3 = (const float*)d_in[23];
    const float* dr_w3  = (const float*)d_in[24];
    const float* dr_b3  = (const float*)d_in[25];
    float* out = (float*)d_out;

    static bool attr_set = false;
    if (!attr_set) {
        cudaFuncSetAttribute(gemm_max_kernel,
                             cudaFuncAttributeMaxDynamicSharedMemorySize,
                             SMEM_BYTES);
        attr_set = true;
    }

    prep_q_kernel<<<MQ, 128>>>(q_patch);
    prep_r_kernel<<<NRP, 128>>>(r_patch);
    adapter_h1_part<<<dim3(K_, 5), 160>>>(r_img, adpt_w1);
    adapter_h1_comb<<<10, 256>>>();
    adapter_out_kernel<<<D_ / 128, 128>>>(adpt_w2);
    gemm_max_kernel<<<dim3(MQ / BM, NSTRIPE), 256, SMEM_BYTES>>>();
    heads_kernel<<<B_, 128>>>(q_img,
                              dh_w1, dh_b1, dh_g2, dh_be2, dh_w2, dh_b2,
                              dh_g3, dh_be3, dh_w3, dh_b3,
                              dr_w1, dr_b1, dr_g2, dr_be2, dr_w2, dr_b2,
                              dr_g3, dr_be3, dr_w3, dr_b3,
                              out);
}

// round 8
// speedup vs baseline: 1.0641x; 1.0641x over previous
#include <cuda_runtime.h>
#include <cuda_fp16.h>
#include <math.h>
#include <stdint.h>

// ---------------------------------------------------------------------------
// Problem constants
// ---------------------------------------------------------------------------
#define B_   64
#define P_   225
#define K_   16
#define D_   640
#define MQ   (B_ * P_)      // 14400 query rows
#define NR   (K_ * P_)      // 3600 reference rows
#define NRP  3648           // NR padded to 57*64
#define NT_  57             // n tiles of 64

// GEMM tiling
#define BM 64
#define BN 64
#define BK 64
#define LDA 648             // A smem row stride (fp16 elems), pad for banks
#define LDB 72              // B smem row stride (144B rows, 16B aligned)
#define NSTRIPE 4

#define A_SMEM_BYTES (BM * LDA * 2)                 // 82944
#define B_SMEM_BYTES (2 * BN * LDB * 2)             // 18432
#define RED_OFF      (A_SMEM_BYTES + B_SMEM_BYTES)  // 101376
#define SMEM_BYTES   (RED_OFF + BM * 5 * 4)         // 102656

// mega-prep block ranges
#define PREP_ADPT_BLKS (K_ * 5)                     // 80
#define PREP_BLOCKS (MQ + NRP + PREP_ADPT_BLKS)     // 18128

// ---------------------------------------------------------------------------
// Scratch (allocation-free: __device__ globals)
// ---------------------------------------------------------------------------
__device__ __half g_qh[MQ * D_];            // raw q_patch in fp16
__device__ __half g_rh[NRP * D_];           // normalized r_patch fp16 (pad 0)
__device__ float g_qnorm[MQ];               // ||q_patch row||
__device__ float g_pmax[NSTRIPE * MQ];      // per-stripe max of q.rn
__device__ float g_h1p[5][K_ * 160];        // adapter partials
__device__ float g_famean[D_];              // mean adapter output

// ---------------------------------------------------------------------------
// helpers
// ---------------------------------------------------------------------------
__device__ __forceinline__ uint32_t smem_u32(const void* p) {
    uint32_t a;
    asm("{ .reg .u64 t; cvta.to.shared.u64 t, %1; cvt.u32.u64 %0, t; }"
        : "=r"(a) : "l"(p));
    return a;
}
__device__ __forceinline__ void cp_async16(uint32_t dst, const void* src) {
    asm volatile("cp.async.cg.shared.global [%0], [%1], 16;"
                 :: "r"(dst), "l"(src) : "memory");
}
#define CP_COMMIT() asm volatile("cp.async.commit_group;" ::: "memory")
#define CP_WAIT0()  asm volatile("cp.async.wait_group 0;" ::: "memory")

// mma.sync fp16 inputs, fp32 accumulate
__device__ __forceinline__ void mma16816(float c[4], const uint32_t a[4],
                                         const uint32_t b[2]) {
    asm volatile(
        "mma.sync.aligned.m16n8k16.row.col.f32.f16.f16.f32 "
        "{%0,%1,%2,%3}, {%4,%5,%6,%7}, {%8,%9}, {%0,%1,%2,%3};\n"
        : "+f"(c[0]), "+f"(c[1]), "+f"(c[2]), "+f"(c[3])
        : "r"(a[0]), "r"(a[1]), "r"(a[2]), "r"(a[3]), "r"(b[0]), "r"(b[1]));
}

// ---------------------------------------------------------------------------
// Kernel 1 (fused prep): prep_q | prep_r | adapter hidden partials
// ---------------------------------------------------------------------------
__global__ void mega_prep_kernel(const float* __restrict__ q_patch,
                                 const float* __restrict__ r_patch,
                                 const float* __restrict__ r_img,
                                 const float* __restrict__ w1) {
    const int bid = blockIdx.x;
    const int t = threadIdx.x;

    if (bid < MQ) {
        // ---- q prep: fp16 convert + row norm ----
        const int row = bid;
        const float4* x4 = (const float4*)(q_patch + (size_t)row * D_);
        __half* o = g_qh + (size_t)row * D_;
        float ss = 0.f;
        for (int i4 = t; i4 < D_ / 4; i4 += 128) {
            float4 v = x4[i4];
            ss = fmaf(v.x, v.x, ss);
            ss = fmaf(v.y, v.y, ss);
            ss = fmaf(v.z, v.z, ss);
            ss = fmaf(v.w, v.w, ss);
            *(__half2*)(o + i4 * 4)     = __floats2half2_rn(v.x, v.y);
            *(__half2*)(o + i4 * 4 + 2) = __floats2half2_rn(v.z, v.w);
        }
        #pragma unroll
        for (int of = 16; of > 0; of >>= 1)
            ss += __shfl_xor_sync(0xffffffffu, ss, of);
        __shared__ float wsum[4];
        if ((t & 31) == 0) wsum[t >> 5] = ss;
        __syncthreads();
        if (t == 0)
            g_qnorm[row] = sqrtf(wsum[0] + wsum[1] + wsum[2] + wsum[3]);
    } else if (bid < MQ + NRP) {
        // ---- r prep: L2 normalize + fp16; zero-fill pad rows ----
        const int row = bid - MQ;
        __half* o = g_rh + (size_t)row * D_;
        if (row >= NR) {
            for (int i = t; i < D_ / 2; i += 128)
                *(__half2*)(o + i * 2) = __floats2half2_rn(0.f, 0.f);
            return;
        }
        const float4* x4 = (const float4*)(r_patch + (size_t)row * D_);
        float ss = 0.f;
        for (int i4 = t; i4 < D_ / 4; i4 += 128) {
            float4 v = x4[i4];
            ss = fmaf(v.x, v.x, ss);
            ss = fmaf(v.y, v.y, ss);
            ss = fmaf(v.z, v.z, ss);
            ss = fmaf(v.w, v.w, ss);
        }
        #pragma unroll
        for (int of = 16; of > 0; of >>= 1)
            ss += __shfl_xor_sync(0xffffffffu, ss, of);
        __shared__ float wsum2[4];
        if ((t & 31) == 0) wsum2[t >> 5] = ss;
        __syncthreads();
        const float scale =
            1.f / (sqrtf(wsum2[0] + wsum2[1] + wsum2[2] + wsum2[3]) + 1e-6f);
        for (int i4 = t; i4 < D_ / 4; i4 += 128) {
            float4 v = x4[i4];
            *(__half2*)(o + i4 * 4)     = __floats2half2_rn(v.x * scale, v.y * scale);
            *(__half2*)(o + i4 * 4 + 2) = __floats2half2_rn(v.z * scale, v.w * scale);
        }
    } else {
        // ---- adapter hidden partials: (k, dc) pair, 128-d chunk ----
        const int idx = bid - MQ - NRP;      // 0..79
        const int k = idx / 5, dc = idx % 5;
        __shared__ float xr[128];
        if (t < 128) xr[t] = r_img[k * D_ + dc * 128 + t];
        __syncthreads();
        #pragma unroll
        for (int rep = 0; rep < 2; ++rep) {
            const int i = t + rep * 128;
            if (i < 160) {
                float s0 = 0.f, s1 = 0.f;
                const float* w = w1 + (size_t)(dc * 128) * 160 + i;
                #pragma unroll 8
                for (int d = 0; d < 128; d += 2) {
                    s0 = fmaf(xr[d], w[(size_t)d * 160], s0);
                    s1 = fmaf(xr[d + 1], w[(size_t)(d + 1) * 160], s1);
                }
                g_h1p[dc][k * 160 + i] = s0 + s1;
            }
        }
    }
}

// ---------------------------------------------------------------------------
// Kernel 2: adapter finish — combine partials + relu, then second layer
// famean[j] = mean_k relu(h1[k] @ w2[:,j]); grid = 5 x 128
// ---------------------------------------------------------------------------
__global__ void adapter_final_kernel(const float* __restrict__ w2) {
    __shared__ float h1s[K_ * 160];
    for (int idx = threadIdx.x; idx < K_ * 160; idx += 128) {
        float s = g_h1p[0][idx] + g_h1p[1][idx] + g_h1p[2][idx] +
                  g_h1p[3][idx] + g_h1p[4][idx];
        h1s[idx] = fmaxf(s, 0.f);
    }
    __syncthreads();
    const int j = blockIdx.x * 128 + threadIdx.x;
    float accm = 0.f;
    for (int k = 0; k < K_; ++k) {
        float s0 = 0.f, s1 = 0.f;
        const float* h = h1s + k * 160;
        #pragma unroll 4
        for (int i = 0; i < 160; i += 2) {
            s0 = fmaf(h[i], w2[i * D_ + j], s0);
            s1 = fmaf(h[i + 1], w2[(i + 1) * D_ + j], s1);
        }
        accm += fmaxf(s0 + s1, 0.f);
    }
    g_famean[j] = accm * (1.f / (float)K_);
}

// ---------------------------------------------------------------------------
// Kernel 3: tensor-core GEMM + row max. fp16 in, fp32 accumulate.
// grid (225, 4): block = 64 q rows x n-stripe. A full-K resident in smem;
// B streamed with cp.async double-buffer, pipeline flattened across n-tiles.
// ---------------------------------------------------------------------------
__global__ __launch_bounds__(256, 2)
void gemm_max_kernel() {
    extern __shared__ __align__(16) char smem[];
    __half* As = (__half*)smem;
    __half* Bs = (__half*)(smem + A_SMEM_BYTES);
    float* red = (float*)(smem + RED_OFF);

    const int tid  = threadIdx.x;
    const int lane = tid & 31;
    const int g    = lane >> 2;     // group id 0..7
    const int tig  = lane & 3;      // thread-in-group 0..3
    const int w    = tid >> 5;
    const int wy   = w >> 2;        // 0..1 (m)
    const int wx   = w & 3;         // 0..3 (n)
    const int rowBase = blockIdx.x * BM;
    const int by = blockIdx.y;

    // ---- load full-K A tile: 64 x 640 fp16 ----
    {
        const __half* gq = g_qh + (size_t)rowBase * D_;
        #pragma unroll
        for (int i = 0; i < 20; ++i) {
            int idx = tid + i * 256;
            int row = idx / 80, kg = idx % 80;
            *(uint4*)(As + row * LDA + kg * 8) =
                *(const uint4*)(gq + (size_t)row * D_ + kg * 8);
        }
    }

    const uint32_t bsBase = smem_u32(Bs);
    const int n0 = tid >> 3, kg0 = tid & 7;   // 32 rows per half, 8 uint4/row
    const int n1 = n0 + 32;

    const int ntiles = (NT_ - by + NSTRIPE - 1) / NSTRIPE;  // 15 or 14
    const int U = ntiles * 10;                               // chunks total

    // ---- prologue: chunk 0 into buf 0 ----
    {
        const __half* s0 = g_rh + ((size_t)(by * BN) + n0) * D_ + kg0 * 8;
        const __half* s1 = g_rh + ((size_t)(by * BN) + n1) * D_ + kg0 * 8;
        cp_async16(bsBase + (uint32_t)(n0 * LDB + kg0 * 8) * 2, s0);
        cp_async16(bsBase + (uint32_t)(n1 * LDB + kg0 * 8) * 2, s1);
        CP_COMMIT();
    }
    CP_WAIT0();
    __syncthreads();   // also covers A-tile visibility

    float rm[2][2] = {{-1e30f, -1e30f}, {-1e30f, -1e30f}};
    float acc[2][2][4];

    int nt = by, kt = 0;
    for (int u = 0; u < U; ++u) {
        // issue copy of chunk u+1 into the other buffer
        int kt1 = kt + 1, nt1 = nt;
        if (kt1 == 10) { kt1 = 0; nt1 = nt + NSTRIPE; }
        if (u + 1 < U) {
            const __half* s0 =
                g_rh + ((size_t)(nt1 * BN) + n0) * D_ + kt1 * BK + kg0 * 8;
            const __half* s1 =
                g_rh + ((size_t)(nt1 * BN) + n1) * D_ + kt1 * BK + kg0 * 8;
            const uint32_t dstb = bsBase + (uint32_t)(((u + 1) & 1) * BN * LDB) * 2;
            cp_async16(dstb + (uint32_t)(n0 * LDB + kg0 * 8) * 2, s0);
            cp_async16(dstb + (uint32_t)(n1 * LDB + kg0 * 8) * 2, s1);
            CP_COMMIT();
        }

        if (kt == 0) {
            #pragma unroll
            for (int i = 0; i < 2; ++i)
                #pragma unroll
                for (int j = 0; j < 2; ++j)
                    #pragma unroll
                    for (int r = 0; r < 4; ++r) acc[i][j][r] = 0.f;
        }

        // ---- compute chunk u ----
        const __half* bufC = Bs + (u & 1) * BN * LDB;
        const int kA0 = kt * BK;
        #pragma unroll
        for (int ks = 0; ks < 4; ++ks) {
            const int kA = kA0 + ks * 16;
            uint32_t a[2][4], b[2][2];
            #pragma unroll
            for (int i = 0; i < 2; ++i) {
                const __half* base =
                    As + (wy * 32 + i * 16 + g) * LDA + kA + tig * 2;
                a[i][0] = *(const uint32_t*)(base);
                a[i][1] = *(const uint32_t*)(base + 8 * LDA);
                a[i][2] = *(const uint32_t*)(base + 8);
                a[i][3] = *(const uint32_t*)(base + 8 * LDA + 8);
            }
            #pragma unroll
            for (int j = 0; j < 2; ++j) {
                const __half* base =
                    bufC + (wx * 16 + j * 8 + g) * LDB + ks * 16 + tig * 2;
                b[j][0] = *(const uint32_t*)(base);
                b[j][1] = *(const uint32_t*)(base + 8);
            }
            #pragma unroll
            for (int i = 0; i < 2; ++i)
                #pragma unroll
                for (int j = 0; j < 2; ++j)
                    mma16816(acc[i][j], a[i], b[j]);
        }

        if (kt == 9) {
            // fold masked max of this n-tile into running max
            const int nBase = nt * BN;
            #pragma unroll
            for (int j = 0; j < 2; ++j) {
                const int c0 = nBase + wx * 16 + j * 8 + tig * 2;
                const bool v0 = (c0 < NR), v1 = (c0 + 1 < NR);
                #pragma unroll
                for (int i = 0; i < 2; ++i) {
                    if (v0) {
                        rm[i][0] = fmaxf(rm[i][0], acc[i][j][0]);
                        rm[i][1] = fmaxf(rm[i][1], acc[i][j][2]);
                    }
                    if (v1) {
                        rm[i][0] = fmaxf(rm[i][0], acc[i][j][1]);
                        rm[i][1] = fmaxf(rm[i][1], acc[i][j][3]);
                    }
                }
            }
        }

        if (u + 1 < U) {
            CP_WAIT0();        // chunk u+1 landed
            __syncthreads();   // all warps done reading buf (u&1) -> reusable
        }
        kt = kt1; nt = nt1;
    }

    // ---- reduce across tig lanes, then across wx warps via smem ----
    #pragma unroll
    for (int i = 0; i < 2; ++i)
        #pragma unroll
        for (int s = 0; s < 2; ++s) {
            float v = rm[i][s];
            v = fmaxf(v, __shfl_xor_sync(0xffffffffu, v, 1));
            v = fmaxf(v, __shfl_xor_sync(0xffffffffu, v, 2));
            rm[i][s] = v;
        }
    __syncthreads();
    if (tig == 0) {
        #pragma unroll
        for (int i = 0; i < 2; ++i)
            #pragma unroll
            for (int s = 0; s < 2; ++s) {
                int row = wy * 32 + i * 16 + s * 8 + g;
                red[row * 5 + wx] = rm[i][s];
            }
    }
    __syncthreads();
    if (tid < BM) {
        float m = red[tid * 5 + 0];
        m = fmaxf(m, red[tid * 5 + 1]);
        m = fmaxf(m, red[tid * 5 + 2]);
        m = fmaxf(m, red[tid * 5 + 3]);
        g_pmax[by * MQ + rowBase + tid] = m;
    }
}

// ---------------------------------------------------------------------------
// Kernel 4: both heads + final score; one block per batch element.
// ---------------------------------------------------------------------------
__global__ void heads_kernel(
    const float* __restrict__ q_img,
    const float* __restrict__ dh_w1, const float* __restrict__ dh_b1,
    const float* __restrict__ dh_g2, const float* __restrict__ dh_be2,
    const float* __restrict__ dh_w2, const float* __restrict__ dh_b2,
    const float* __restrict__ dh_g3, const float* __restrict__ dh_be3,
    const float* __restrict__ dh_w3, const float* __restrict__ dh_b3,
    const float* __restrict__ dr_w1, const float* __restrict__ dr_b1,
    const float* __restrict__ dr_g2, const float* __restrict__ dr_be2,
    const float* __restrict__ dr_w2, const float* __restrict__ dr_b2,
    const float* __restrict__ dr_g3, const float* __restrict__ dr_be3,
    const float* __restrict__ dr_w3, const float* __restrict__ dr_b3,
    float* __restrict__ out) {
    const int b = blockIdx.x;
    const int t = threadIdx.x;          // 128 threads
    __shared__ float xr[D_];
    __shared__ float am[P_];
    __shared__ float h1[128];
    __shared__ float h2[64];
    __shared__ float s_ref_s, s_map_s, mean_s;

    for (int i = t; i < D_; i += 128) xr[i] = q_img[b * D_ + i] - g_famean[i];
    for (int i = t; i < P_; i += 128) {
        const int r = b * P_ + i;
        float mx = g_pmax[r];
        mx = fmaxf(mx, g_pmax[MQ + r]);
        mx = fmaxf(mx, g_pmax[2 * MQ + r]);
        mx = fmaxf(mx, g_pmax[3 * MQ + r]);
        am[i] = 0.5f * (1.f - mx / (g_qnorm[r] + 1e-6f));
    }
    __syncthreads();

    // ---- dr head on xr (640 -> 128 -> 64 -> 1) ----
    {
        float s = dr_b1[t];
        for (int d = 0; d < D_; ++d) s = fmaf(xr[d], dr_w1[d * 128 + t], s);
        h1[t] = fmaxf(s, 0.f) * dr_g2[t] + dr_be2[t];
    }
    __syncthreads();
    if (t < 64) {
        float s = dr_b2[t];
        for (int i = 0; i < 128; ++i) s = fmaf(h1[i], dr_w2[i * 64 + t], s);
        h2[t] = fmaxf(s, 0.f) * dr_g3[t] + dr_be3[t];
    }
    __syncthreads();
    if (t == 0) {
        float s = dr_b3[0];
        for (int i = 0; i < 64; ++i) s = fmaf(h2[i], dr_w3[i], s);
        s_ref_s = 1.f / (1.f + expf(-s));
    }
    __syncthreads();

    // ---- dh head on am (225 -> 128 -> 64 -> 1) ----
    {
        float s = dh_b1[t];
        for (int p = 0; p < P_; ++p) s = fmaf(am[p], dh_w1[p * 128 + t], s);
        h1[t] = fmaxf(s, 0.f) * dh_g2[t] + dh_be2[t];
    }
    __syncthreads();
    if (t < 64) {
        float s = dh_b2[t];
        for (int i = 0; i < 128; ++i) s = fmaf(h1[i], dh_w2[i * 64 + t], s);
        h2[t] = fmaxf(s, 0.f) * dh_g3[t] + dh_be3[t];
    }
    __syncthreads();
    if (t == 0) {
        float s = dh_b3[0];
        for (int i = 0; i < 64; ++i) s = fmaf(h2[i], dh_w3[i], s);
        s_map_s = 1.f / (1.f + expf(-s));
        float msum = 0.f;
        for (int p = 0; p < P_; ++p) msum += am[p];
        mean_s = msum / (float)P_;
        out[b] = 0.5f * (s_ref_s + s_map_s) + mean_s;
    }
}

// ---------------------------------------------------------------------------
// Launch
// ---------------------------------------------------------------------------
extern "C" void kernel_launch(void* const* d_in, const int* in_sizes, int n_in,
                              void* d_out, int out_size) {
    const float* q_patch = (const float*)d_in[0];
    const float* r_patch = (const float*)d_in[1];
    const float* q_img   = (const float*)d_in[2];
    const float* r_img   = (const float*)d_in[3];
    const float* adpt_w1 = (const float*)d_in[4];
    const float* adpt_w2 = (const float*)d_in[5];
    const float* dh_w1  = (const float*)d_in[6];
    const float* dh_b1  = (const float*)d_in[7];
    const float* dh_g2  = (const float*)d_in[8];
    const float* dh_be2 = (const float*)d_in[9];
    const float* dh_w2  = (const float*)d_in[10];
    const float* dh_b2  = (const float*)d_in[11];
    const float* dh_g3  = (const float*)d_in[12];
    const float* dh_be3 = (const float*)d_in[13];
    const float* dh_w3  = (const float*)d_in[14];
    const float* dh_b3  = (const float*)d_in[15];
    const float* dr_w1  = (const float*)d_in[16];
    const float* dr_b1  = (const float*)d_in[17];
    const float* dr_g2  = (const float*)d_in[18];
    const float* dr_be2 = (const float*)d_in[19];
    const float* dr_w2  = (const float*)d_in[20];
    const float* dr_b2  = (const float*)d_in[21];
    const float* dr_g3  = (const float*)d_in[22];
    const float* dr_be3 = (const float*)d_in[23];
    const float* dr_w3  = (const float*)d_in[24];
    const float* dr_b3  = (const float*)d_in[25];
    float* out = (float*)d_out;

    static bool attr_set = false;
    if (!attr_set) {
        cudaFuncSetAttribute(gemm_max_kernel,
                             cudaFuncAttributeMaxDynamicSharedMemorySize,
                             SMEM_BYTES);
        attr_set = true;
    }

    mega_prep_kernel<<<PREP_BLOCKS, 128>>>(q_patch, r_patch, r_img, adpt_w1);
    adapter_final_kernel<<<D_ / 128, 128>>>(adpt_w2);
    gemm_max_kernel<<<dim3(MQ / BM, NSTRIPE), 256, SMEM_BYTES>>>();
    heads_kernel<<<B_, 128>>>(q_img,
                              dh_w1, dh_b1, dh_g2, dh_be2, dh_w2, dh_b2,
                              dh_g3, dh_be3, dh_w3, dh_b3,
                              dr_w1, dr_b1, dr_g2, dr_be2, dr_w2, dr_b2,
                              dr_g3, dr_be3, dr_w3, dr_b3,
                              out);
}

// round 9
// speedup vs baseline: 1.1611x; 1.0911x over previous
#include <cuda_runtime.h>
#include <cuda_fp16.h>
#include <math.h>
#include <stdint.h>

// ---------------------------------------------------------------------------
// Problem constants
// ---------------------------------------------------------------------------
#define B_   64
#define P_   225
#define K_   16
#define D_   640
#define MQ   (B_ * P_)      // 14400 query rows
#define NR   (K_ * P_)      // 3600 reference rows
#define NRP  3648           // NR padded to 57*64
#define NT_  57             // n tiles of 64

// GEMM tiling
#define BM 64
#define BN 64
#define BK 64
#define LDA 648             // A smem row stride (fp16), row stride = 4 banks
#define LDB 72              // B smem row stride (144B), row stride = 4 banks
#define NSTRIPE 4

#define A_SMEM_BYTES (BM * LDA * 2)                 // 82944
#define B_SMEM_BYTES (2 * BN * LDB * 2)             // 18432
#define RED_OFF      (A_SMEM_BYTES + B_SMEM_BYTES)  // 101376
#define SMEM_BYTES   (RED_OFF + BM * 5 * 4)         // 102656

// mega-prep block ranges
#define PREP_ADPT_BLKS (K_ * 5)                     // 80
#define PREP_BLOCKS (MQ + NRP + PREP_ADPT_BLKS)     // 18128

// ---------------------------------------------------------------------------
// Scratch (allocation-free: __device__ globals)
// ---------------------------------------------------------------------------
__device__ __half g_qh[MQ * D_];            // raw q_patch in fp16
__device__ __half g_rh[NRP * D_];           // normalized r_patch fp16 (pad 0)
__device__ float g_qnorm[MQ];               // ||q_patch row||
__device__ float g_pmax[NSTRIPE * MQ];      // per-stripe max of q.rn
__device__ float g_h1p[5][K_ * 160];        // adapter partials
__device__ float g_famean[D_];              // mean adapter output

// ---------------------------------------------------------------------------
// helpers
// ---------------------------------------------------------------------------
__device__ __forceinline__ uint32_t smem_u32(const void* p) {
    uint32_t a;
    asm("{ .reg .u64 t; cvta.to.shared.u64 t, %1; cvt.u32.u64 %0, t; }"
        : "=r"(a) : "l"(p));
    return a;
}
__device__ __forceinline__ void cp_async16(uint32_t dst, const void* src) {
    asm volatile("cp.async.cg.shared.global [%0], [%1], 16;"
                 :: "r"(dst), "l"(src) : "memory");
}
#define CP_COMMIT() asm volatile("cp.async.commit_group;" ::: "memory")
#define CP_WAIT0()  asm volatile("cp.async.wait_group 0;" ::: "memory")

__device__ __forceinline__ void ldsm_x4(uint32_t r[4], uint32_t addr) {
    asm volatile("ldmatrix.sync.aligned.m8n8.x4.shared.b16 {%0,%1,%2,%3}, [%4];"
                 : "=r"(r[0]), "=r"(r[1]), "=r"(r[2]), "=r"(r[3]) : "r"(addr));
}
__device__ __forceinline__ void ldsm_x2(uint32_t r[2], uint32_t addr) {
    asm volatile("ldmatrix.sync.aligned.m8n8.x2.shared.b16 {%0,%1}, [%2];"
                 : "=r"(r[0]), "=r"(r[1]) : "r"(addr));
}

// mma.sync fp16 inputs, fp32 accumulate
__device__ __forceinline__ void mma16816(float c[4], const uint32_t a[4],
                                         const uint32_t b[2]) {
    asm volatile(
        "mma.sync.aligned.m16n8k16.row.col.f32.f16.f16.f32 "
        "{%0,%1,%2,%3}, {%4,%5,%6,%7}, {%8,%9}, {%0,%1,%2,%3};\n"
        : "+f"(c[0]), "+f"(c[1]), "+f"(c[2]), "+f"(c[3])
        : "r"(a[0]), "r"(a[1]), "r"(a[2]), "r"(a[3]), "r"(b[0]), "r"(b[1]));
}

// ---------------------------------------------------------------------------
// Kernel 1 (fused prep): prep_q | prep_r | adapter hidden partials
// ---------------------------------------------------------------------------
__global__ void mega_prep_kernel(const float* __restrict__ q_patch,
                                 const float* __restrict__ r_patch,
                                 const float* __restrict__ r_img,
                                 const float* __restrict__ w1) {
    const int bid = blockIdx.x;
    const int t = threadIdx.x;

    if (bid < MQ) {
        const int row = bid;
        const float4* x4 = (const float4*)(q_patch + (size_t)row * D_);
        __half* o = g_qh + (size_t)row * D_;
        float ss = 0.f;
        for (int i4 = t; i4 < D_ / 4; i4 += 128) {
            float4 v = x4[i4];
            ss = fmaf(v.x, v.x, ss);
            ss = fmaf(v.y, v.y, ss);
            ss = fmaf(v.z, v.z, ss);
            ss = fmaf(v.w, v.w, ss);
            *(__half2*)(o + i4 * 4)     = __floats2half2_rn(v.x, v.y);
            *(__half2*)(o + i4 * 4 + 2) = __floats2half2_rn(v.z, v.w);
        }
        #pragma unroll
        for (int of = 16; of > 0; of >>= 1)
            ss += __shfl_xor_sync(0xffffffffu, ss, of);
        __shared__ float wsum[4];
        if ((t & 31) == 0) wsum[t >> 5] = ss;
        __syncthreads();
        if (t == 0)
            g_qnorm[row] = sqrtf(wsum[0] + wsum[1] + wsum[2] + wsum[3]);
    } else if (bid < MQ + NRP) {
        const int row = bid - MQ;
        __half* o = g_rh + (size_t)row * D_;
        if (row >= NR) {
            for (int i = t; i < D_ / 2; i += 128)
                *(__half2*)(o + i * 2) = __floats2half2_rn(0.f, 0.f);
            return;
        }
        const float4* x4 = (const float4*)(r_patch + (size_t)row * D_);
        float ss = 0.f;
        for (int i4 = t; i4 < D_ / 4; i4 += 128) {
            float4 v = x4[i4];
            ss = fmaf(v.x, v.x, ss);
            ss = fmaf(v.y, v.y, ss);
            ss = fmaf(v.z, v.z, ss);
            ss = fmaf(v.w, v.w, ss);
        }
        #pragma unroll
        for (int of = 16; of > 0; of >>= 1)
            ss += __shfl_xor_sync(0xffffffffu, ss, of);
        __shared__ float wsum2[4];
        if ((t & 31) == 0) wsum2[t >> 5] = ss;
        __syncthreads();
        const float scale =
            1.f / (sqrtf(wsum2[0] + wsum2[1] + wsum2[2] + wsum2[3]) + 1e-6f);
        for (int i4 = t; i4 < D_ / 4; i4 += 128) {
            float4 v = x4[i4];
            *(__half2*)(o + i4 * 4)     = __floats2half2_rn(v.x * scale, v.y * scale);
            *(__half2*)(o + i4 * 4 + 2) = __floats2half2_rn(v.z * scale, v.w * scale);
        }
    } else {
        const int idx = bid - MQ - NRP;      // 0..79
        const int k = idx / 5, dc = idx % 5;
        __shared__ float xr[128];
        if (t < 128) xr[t] = r_img[k * D_ + dc * 128 + t];
        __syncthreads();
        #pragma unroll
        for (int rep = 0; rep < 2; ++rep) {
            const int i = t + rep * 128;
            if (i < 160) {
                float s0 = 0.f, s1 = 0.f;
                const float* w = w1 + (size_t)(dc * 128) * 160 + i;
                #pragma unroll 8
                for (int d = 0; d < 128; d += 2) {
                    s0 = fmaf(xr[d], w[(size_t)d * 160], s0);
                    s1 = fmaf(xr[d + 1], w[(size_t)(d + 1) * 160], s1);
                }
                g_h1p[dc][k * 160 + i] = s0 + s1;
            }
        }
    }
}

// ---------------------------------------------------------------------------
// Kernel 2: adapter finish — combine partials + relu, then second layer
// ---------------------------------------------------------------------------
__global__ void adapter_final_kernel(const float* __restrict__ w2) {
    __shared__ float h1s[K_ * 160];
    for (int idx = threadIdx.x; idx < K_ * 160; idx += 128) {
        float s = g_h1p[0][idx] + g_h1p[1][idx] + g_h1p[2][idx] +
                  g_h1p[3][idx] + g_h1p[4][idx];
        h1s[idx] = fmaxf(s, 0.f);
    }
    __syncthreads();
    const int j = blockIdx.x * 128 + threadIdx.x;
    float accm = 0.f;
    for (int k = 0; k < K_; ++k) {
        float s0 = 0.f, s1 = 0.f;
        const float* h = h1s + k * 160;
        #pragma unroll 4
        for (int i = 0; i < 160; i += 2) {
            s0 = fmaf(h[i], w2[i * D_ + j], s0);
            s1 = fmaf(h[i + 1], w2[(i + 1) * D_ + j], s1);
        }
        accm += fmaxf(s0 + s1, 0.f);
    }
    g_famean[j] = accm * (1.f / (float)K_);
}

// ---------------------------------------------------------------------------
// Kernel 3: tensor-core GEMM + row max. fp16 in, fp32 acc, ldmatrix operands.
// ---------------------------------------------------------------------------
__global__ __launch_bounds__(256, 2)
void gemm_max_kernel() {
    extern __shared__ __align__(16) char smem[];
    __half* As = (__half*)smem;
    __half* Bs = (__half*)(smem + A_SMEM_BYTES);
    float* red = (float*)(smem + RED_OFF);

    const int tid  = threadIdx.x;
    const int lane = tid & 31;
    const int g    = lane >> 2;
    const int tig  = lane & 3;
    const int w    = tid >> 5;
    const int wy   = w >> 2;        // 0..1 (m)
    const int wx   = w & 3;         // 0..3 (n)
    const int rowBase = blockIdx.x * BM;
    const int by = blockIdx.y;

    // ---- load full-K A tile: 64 x 640 fp16 ----
    {
        const __half* gq = g_qh + (size_t)rowBase * D_;
        #pragma unroll
        for (int i = 0; i < 20; ++i) {
            int idx = tid + i * 256;
            int row = idx / 80, kg = idx % 80;
            *(uint4*)(As + row * LDA + kg * 8) =
                *(const uint4*)(gq + (size_t)row * D_ + kg * 8);
        }
    }

    const uint32_t sbA = smem_u32(As);
    const uint32_t bsBase = smem_u32(Bs);

    // ldmatrix per-lane addresses
    const int aRow = (lane & 7) + ((lane >> 3) & 1) * 8;   // 0..15
    const int aCol = (lane >> 4) * 8;                       // 0 or 8
    uint32_t aAddr[2];
    #pragma unroll
    for (int i = 0; i < 2; ++i)
        aAddr[i] = sbA +
            (uint32_t)(((wy * 32 + i * 16 + aRow) * LDA + aCol) * 2);
    const int bRow = lane & 7;
    const int bCol = ((lane >> 3) & 1) * 8;
    uint32_t bAddr[2];
    #pragma unroll
    for (int j = 0; j < 2; ++j)
        bAddr[j] = bsBase +
            (uint32_t)(((wx * 16 + j * 8 + bRow) * LDB + bCol) * 2);

    const int n0 = tid >> 3, kg0 = tid & 7;   // cp.async indices
    const int n1 = n0 + 32;

    const int ntiles = (NT_ - by + NSTRIPE - 1) / NSTRIPE;
    const int U = ntiles * 10;

    // ---- prologue: chunk 0 into buf 0 ----
    {
        const __half* s0 = g_rh + ((size_t)(by * BN) + n0) * D_ + kg0 * 8;
        const __half* s1 = g_rh + ((size_t)(by * BN) + n1) * D_ + kg0 * 8;
        cp_async16(bsBase + (uint32_t)(n0 * LDB + kg0 * 8) * 2, s0);
        cp_async16(bsBase + (uint32_t)(n1 * LDB + kg0 * 8) * 2, s1);
        CP_COMMIT();
    }
    CP_WAIT0();
    __syncthreads();

    float rm[2][2] = {{-1e30f, -1e30f}, {-1e30f, -1e30f}};
    float acc[2][2][4];

    int nt = by, kt = 0;
    for (int u = 0; u < U; ++u) {
        int kt1 = kt + 1, nt1 = nt;
        if (kt1 == 10) { kt1 = 0; nt1 = nt + NSTRIPE; }
        if (u + 1 < U) {
            const __half* s0 =
                g_rh + ((size_t)(nt1 * BN) + n0) * D_ + kt1 * BK + kg0 * 8;
            const __half* s1 =
                g_rh + ((size_t)(nt1 * BN) + n1) * D_ + kt1 * BK + kg0 * 8;
            const uint32_t dstb = bsBase + (uint32_t)(((u + 1) & 1) * BN * LDB) * 2;
            cp_async16(dstb + (uint32_t)(n0 * LDB + kg0 * 8) * 2, s0);
            cp_async16(dstb + (uint32_t)(n1 * LDB + kg0 * 8) * 2, s1);
            CP_COMMIT();
        }

        if (kt == 0) {
            #pragma unroll
            for (int i = 0; i < 2; ++i)
                #pragma unroll
                for (int j = 0; j < 2; ++j)
                    #pragma unroll
                    for (int r = 0; r < 4; ++r) acc[i][j][r] = 0.f;
        }

        // ---- compute chunk u (ldmatrix operands) ----
        const uint32_t bufOff = (uint32_t)((u & 1) * BN * LDB) * 2;
        const int kA0 = kt * BK;
        #pragma unroll
        for (int ks = 0; ks < 4; ++ks) {
            const uint32_t kOffA = (uint32_t)(kA0 + ks * 16) * 2;
            const uint32_t kOffB = bufOff + (uint32_t)(ks * 16) * 2;
            uint32_t a[2][4], b[2][2];
            ldsm_x4(a[0], aAddr[0] + kOffA);
            ldsm_x4(a[1], aAddr[1] + kOffA);
            ldsm_x2(b[0], bAddr[0] + kOffB);
            ldsm_x2(b[1], bAddr[1] + kOffB);
            #pragma unroll
            for (int i = 0; i < 2; ++i)
                #pragma unroll
                for (int j = 0; j < 2; ++j)
                    mma16816(acc[i][j], a[i], b[j]);
        }

        if (kt == 9) {
            const int nBase = nt * BN;
            #pragma unroll
            for (int j = 0; j < 2; ++j) {
                const int c0 = nBase + wx * 16 + j * 8 + tig * 2;
                const bool v0 = (c0 < NR), v1 = (c0 + 1 < NR);
                #pragma unroll
                for (int i = 0; i < 2; ++i) {
                    if (v0) {
                        rm[i][0] = fmaxf(rm[i][0], acc[i][j][0]);
                        rm[i][1] = fmaxf(rm[i][1], acc[i][j][2]);
                    }
                    if (v1) {
                        rm[i][0] = fmaxf(rm[i][0], acc[i][j][1]);
                        rm[i][1] = fmaxf(rm[i][1], acc[i][j][3]);
                    }
                }
            }
        }

        if (u + 1 < U) {
            CP_WAIT0();
            __syncthreads();
        }
        kt = kt1; nt = nt1;
    }

    // ---- reduce across tig lanes, then across wx warps via smem ----
    #pragma unroll
    for (int i = 0; i < 2; ++i)
        #pragma unroll
        for (int s = 0; s < 2; ++s) {
            float v = rm[i][s];
            v = fmaxf(v, __shfl_xor_sync(0xffffffffu, v, 1));
            v = fmaxf(v, __shfl_xor_sync(0xffffffffu, v, 2));
            rm[i][s] = v;
        }
    __syncthreads();
    if (tig == 0) {
        #pragma unroll
        for (int i = 0; i < 2; ++i)
            #pragma unroll
            for (int s = 0; s < 2; ++s) {
                int row = wy * 32 + i * 16 + s * 8 + g;
                red[row * 5 + wx] = rm[i][s];
            }
    }
    __syncthreads();
    if (tid < BM) {
        float m = red[tid * 5 + 0];
        m = fmaxf(m, red[tid * 5 + 1]);
        m = fmaxf(m, red[tid * 5 + 2]);
        m = fmaxf(m, red[tid * 5 + 3]);
        g_pmax[by * MQ + rowBase + tid] = m;
    }
}

// ---------------------------------------------------------------------------
// Kernel 4: both heads + final score; 256 threads, d-split parallel layers.
// ---------------------------------------------------------------------------
__global__ __launch_bounds__(256)
void heads_kernel(
    const float* __restrict__ q_img,
    const float* __restrict__ dh_w1, const float* __restrict__ dh_b1,
    const float* __restrict__ dh_g2, const float* __restrict__ dh_be2,
    const float* __restrict__ dh_w2, const float* __restrict__ dh_b2,
    const float* __restrict__ dh_g3, const float* __restrict__ dh_be3,
    const float* __restrict__ dh_w3, const float* __restrict__ dh_b3,
    const float* __restrict__ dr_w1, const float* __restrict__ dr_b1,
    const float* __restrict__ dr_g2, const float* __restrict__ dr_be2,
    const float* __restrict__ dr_w2, const float* __restrict__ dr_b2,
    const float* __restrict__ dr_g3, const float* __restrict__ dr_be3,
    const float* __restrict__ dr_w3, const float* __restrict__ dr_b3,
    float* __restrict__ out) {
    const int b = blockIdx.x;
    const int t = threadIdx.x;          // 256 threads
    __shared__ float xr[D_];
    __shared__ float am[P_];
    __shared__ float part[256];
    __shared__ float h1[128];
    __shared__ float h2[64];
    __shared__ float red8[8];
    __shared__ float s_ref_s, mean_s;

    for (int i = t; i < D_; i += 256) xr[i] = q_img[b * D_ + i] - g_famean[i];
    for (int i = t; i < P_; i += 256) {
        const int r = b * P_ + i;
        float mx = g_pmax[r];
        mx = fmaxf(mx, g_pmax[MQ + r]);
        mx = fmaxf(mx, g_pmax[2 * MQ + r]);
        mx = fmaxf(mx, g_pmax[3 * MQ + r]);
        am[i] = 0.5f * (1.f - mx / (g_qnorm[r] + 1e-6f));
    }
    __syncthreads();

    // ---- mean of am (block reduce) ----
    {
        float s = (t < P_) ? am[t] : 0.f;
        #pragma unroll
        for (int o = 16; o > 0; o >>= 1) s += __shfl_xor_sync(0xffffffffu, s, o);
        if ((t & 31) == 0) red8[t >> 5] = s;
    }
    __syncthreads();
    if (t == 0) {
        float m = 0.f;
        #pragma unroll
        for (int i = 0; i < 8; ++i) m += red8[i];
        mean_s = m / (float)P_;
    }

    // ---- dr head L1: 640 -> 128 (d-split x2, 4 accumulators) ----
    {
        const int t2 = t & 127, half = t >> 7;
        const float* wp = dr_w1 + t2;
        const int d0 = half * 320;
        float s0 = 0.f, s1 = 0.f, s2 = 0.f, s3 = 0.f;
        #pragma unroll 4
        for (int d = 0; d < 320; d += 4) {
            s0 = fmaf(xr[d0 + d + 0], wp[(size_t)(d0 + d + 0) * 128], s0);
            s1 = fmaf(xr[d0 + d + 1], wp[(size_t)(d0 + d + 1) * 128], s1);
            s2 = fmaf(xr[d0 + d + 2], wp[(size_t)(d0 + d + 2) * 128], s2);
            s3 = fmaf(xr[d0 + d + 3], wp[(size_t)(d0 + d + 3) * 128], s3);
        }
        part[t] = (s0 + s1) + (s2 + s3);
    }
    __syncthreads();
    if (t < 128)
        h1[t] = fmaxf(part[t] + part[t + 128] + dr_b1[t], 0.f) * dr_g2[t] + dr_be2[t];
    __syncthreads();
    // dr L2: 128 -> 64 (split x2)
    if (t < 128) {
        const int t2 = t & 63, half = t >> 6;
        const float* wp = dr_w2 + t2;
        const int i0 = half * 64;
        float s0 = 0.f, s1 = 0.f;
        #pragma unroll 8
        for (int i = 0; i < 64; i += 2) {
            s0 = fmaf(h1[i0 + i], wp[(size_t)(i0 + i) * 64], s0);
            s1 = fmaf(h1[i0 + i + 1], wp[(size_t)(i0 + i + 1) * 64], s1);
        }
        part[t] = s0 + s1;
    }
    __syncthreads();
    if (t < 64)
        h2[t] = fmaxf(part[t] + part[t + 64] + dr_b2[t], 0.f) * dr_g3[t] + dr_be3[t];
    __syncthreads();
    if (t < 32) {
        float s = h2[t] * dr_w3[t] + h2[t + 32] * dr_w3[t + 32];
        #pragma unroll
        for (int o = 16; o > 0; o >>= 1) s += __shfl_xor_sync(0xffffffffu, s, o);
        if (t == 0) s_ref_s = 1.f / (1.f + expf(-(s + dr_b3[0])));
    }
    __syncthreads();

    // ---- dh head L1: 225 -> 128 (p-split even/odd, 2 accumulators) ----
    {
        const int t2 = t & 127, half = t >> 7;
        const float* wp = dh_w1 + t2;
        float s0 = 0.f, s1 = 0.f;
        int p = half;
        for (; p + 2 < P_; p += 4) {
            s0 = fmaf(am[p], wp[(size_t)p * 128], s0);
            s1 = fmaf(am[p + 2], wp[(size_t)(p + 2) * 128], s1);
        }
        if (p < P_) s0 = fmaf(am[p], wp[(size_t)p * 128], s0);
        part[t] = s0 + s1;
    }
    __syncthreads();
    if (t < 128)
        h1[t] = fmaxf(part[t] + part[t + 128] + dh_b1[t], 0.f) * dh_g2[t] + dh_be2[t];
    __syncthreads();
    // dh L2: 128 -> 64 (split x2)
    if (t < 128) {
        const int t2 = t & 63, half = t >> 6;
        const float* wp = dh_w2 + t2;
        const int i0 = half * 64;
        float s0 = 0.f, s1 = 0.f;
        #pragma unroll 8
        for (int i = 0; i < 64; i += 2) {
            s0 = fmaf(h1[i0 + i], wp[(size_t)(i0 + i) * 64], s0);
            s1 = fmaf(h1[i0 + i + 1], wp[(size_t)(i0 + i + 1) * 64], s1);
        }
        part[t] = s0 + s1;
    }
    __syncthreads();
    if (t < 64)
        h2[t] = fmaxf(part[t] + part[t + 64] + dh_b2[t], 0.f) * dh_g3[t] + dh_be3[t];
    __syncthreads();
    if (t < 32) {
        float s = h2[t] * dh_w3[t] + h2[t + 32] * dh_w3[t + 32];
        #pragma unroll
        for (int o = 16; o > 0; o >>= 1) s += __shfl_xor_sync(0xffffffffu, s, o);
        if (t == 0) {
            float s_map = 1.f / (1.f + expf(-(s + dh_b3[0])));
            out[b] = 0.5f * (s_ref_s + s_map) + mean_s;
        }
    }
}

// ---------------------------------------------------------------------------
// Launch
// ---------------------------------------------------------------------------
extern "C" void kernel_launch(void* const* d_in, const int* in_sizes, int n_in,
                              void* d_out, int out_size) {
    const float* q_patch = (const float*)d_in[0];
    const float* r_patch = (const float*)d_in[1];
    const float* q_img   = (const float*)d_in[2];
    const float* r_img   = (const float*)d_in[3];
    const float* adpt_w1 = (const float*)d_in[4];
    const float* adpt_w2 = (const float*)d_in[5];
    const float* dh_w1  = (const float*)d_in[6];
    const float* dh_b1  = (const float*)d_in[7];
    const float* dh_g2  = (const float*)d_in[8];
    const float* dh_be2 = (const float*)d_in[9];
    const float* dh_w2  = (const float*)d_in[10];
    const float* dh_b2  = (const float*)d_in[11];
    const float* dh_g3  = (const float*)d_in[12];
    const float* dh_be3 = (const float*)d_in[13];
    const float* dh_w3  = (const float*)d_in[14];
    const float* dh_b3  = (const float*)d_in[15];
    const float* dr_w1  = (const float*)d_in[16];
    const float* dr_b1  = (const float*)d_in[17];
    const float* dr_g2  = (const float*)d_in[18];
    const float* dr_be2 = (const float*)d_in[19];
    const float* dr_w2  = (const float*)d_in[20];
    const float* dr_b2  = (const float*)d_in[21];
    const float* dr_g3  = (const float*)d_in[22];
    const float* dr_be3 = (const float*)d_in[23];
    const float* dr_w3  = (const float*)d_in[24];
    const float* dr_b3  = (const float*)d_in[25];
    float* out = (float*)d_out;

    static bool attr_set = false;
    if (!attr_set) {
        cudaFuncSetAttribute(gemm_max_kernel,
                             cudaFuncAttributeMaxDynamicSharedMemorySize,
                             SMEM_BYTES);
        attr_set = true;
    }

    mega_prep_kernel<<<PREP_BLOCKS, 128>>>(q_patch, r_patch, r_img, adpt_w1);
    adapter_final_kernel<<<D_ / 128, 128>>>(adpt_w2);
    gemm_max_kernel<<<dim3(MQ / BM, NSTRIPE), 256, SMEM_BYTES>>>();
    heads_kernel<<<B_, 256>>>(q_img,
                              dh_w1, dh_b1, dh_g2, dh_be2, dh_w2, dh_b2,
                              dh_g3, dh_be3, dh_w3, dh_b3,
                              dr_w1, dr_b1, dr_g2, dr_be2, dr_w2, dr_b2,
                              dr_g3, dr_be3, dr_w3, dr_b3,
                              out);
}

// round 10
// speedup vs baseline: 1.1903x; 1.0251x over previous
#include <cuda_runtime.h>
#include <cuda_fp16.h>
#include <math.h>
#include <stdint.h>

// ---------------------------------------------------------------------------
// Problem constants
// ---------------------------------------------------------------------------
#define B_   64
#define P_   225
#define K_   16
#define D_   640
#define MQ   (B_ * P_)      // 14400 query rows
#define NR   (K_ * P_)      // 3600 reference rows
#define NRP  3648           // NR padded to 57*64
#define NT_  57             // n tiles of 64

// GEMM tiling
#define BM 64
#define BN 64
#define BK 64
#define LDA 648             // A smem row stride (fp16), row stride = 4 banks
#define LDB 72              // B smem row stride (144B), row stride = 4 banks
#define NSTRIPE 4

#define A_SMEM_BYTES (BM * LDA * 2)                 // 82944
#define B_SMEM_BYTES (2 * BN * LDB * 2)             // 18432
#define RED_OFF      (A_SMEM_BYTES + B_SMEM_BYTES)  // 101376
#define SMEM_BYTES   (RED_OFF + BM * 5 * 4)         // 102656

// prep: 16 rows per 512-thread block (warp per row) + adapter tail blocks
#define ROWBLKS ((MQ + NRP) / 16)                   // 1128
#define ADPT_BLKS 20                                // 80 (k,dc) pairs / 4
#define PREP_BLOCKS (ROWBLKS + ADPT_BLKS)           // 1148

// ---------------------------------------------------------------------------
// Scratch (allocation-free: __device__ globals)
// ---------------------------------------------------------------------------
__device__ __half g_qh[MQ * D_];            // raw q_patch in fp16
__device__ __half g_rh[NRP * D_];           // normalized r_patch fp16 (pad 0)
__device__ float g_qnorm[MQ];               // ||q_patch row||
__device__ float g_pmax[NSTRIPE * MQ];      // per-stripe max of q.rn
__device__ float g_h1p[5][K_ * 160];        // adapter partials
__device__ float g_famean[D_];              // mean adapter output

// ---------------------------------------------------------------------------
// helpers
// ---------------------------------------------------------------------------
__device__ __forceinline__ uint32_t smem_u32(const void* p) {
    uint32_t a;
    asm("{ .reg .u64 t; cvta.to.shared.u64 t, %1; cvt.u32.u64 %0, t; }"
        : "=r"(a) : "l"(p));
    return a;
}
__device__ __forceinline__ void cp_async16(uint32_t dst, const void* src) {
    asm volatile("cp.async.cg.shared.global [%0], [%1], 16;"
                 :: "r"(dst), "l"(src) : "memory");
}
#define CP_COMMIT() asm volatile("cp.async.commit_group;" ::: "memory")
#define CP_WAIT0()  asm volatile("cp.async.wait_group 0;" ::: "memory")

__device__ __forceinline__ void ldsm_x4(uint32_t r[4], uint32_t addr) {
    asm volatile("ldmatrix.sync.aligned.m8n8.x4.shared.b16 {%0,%1,%2,%3}, [%4];"
                 : "=r"(r[0]), "=r"(r[1]), "=r"(r[2]), "=r"(r[3]) : "r"(addr));
}
__device__ __forceinline__ void ldsm_x2(uint32_t r[2], uint32_t addr) {
    asm volatile("ldmatrix.sync.aligned.m8n8.x2.shared.b16 {%0,%1}, [%2];"
                 : "=r"(r[0]), "=r"(r[1]) : "r"(addr));
}

// mma.sync fp16 inputs, fp32 accumulate
__device__ __forceinline__ void mma16816(float c[4], const uint32_t a[4],
                                         const uint32_t b[2]) {
    asm volatile(
        "mma.sync.aligned.m16n8k16.row.col.f32.f16.f16.f32 "
        "{%0,%1,%2,%3}, {%4,%5,%6,%7}, {%8,%9}, {%0,%1,%2,%3};\n"
        : "+f"(c[0]), "+f"(c[1]), "+f"(c[2]), "+f"(c[3])
        : "r"(a[0]), "r"(a[1]), "r"(a[2]), "r"(a[3]), "r"(b[0]), "r"(b[1]));
}

// ---------------------------------------------------------------------------
// Kernel 1 (fused prep): warp-per-row q/r prep + adapter hidden partials
// ---------------------------------------------------------------------------
__global__ __launch_bounds__(512)
void mega_prep_kernel(const float* __restrict__ q_patch,
                      const float* __restrict__ r_patch,
                      const float* __restrict__ r_img,
                      const float* __restrict__ w1) {
    const int t = threadIdx.x;

    if (blockIdx.x < ROWBLKS) {
        const int lane = t & 31;
        const int row = blockIdx.x * 16 + (t >> 5);
        if (row < MQ) {
            // ---- q row: fp16 convert + norm ----
            const float4* x4 = (const float4*)(q_patch + (size_t)row * D_);
            __half* o = g_qh + (size_t)row * D_;
            float4 v[5];
            float ss = 0.f;
            #pragma unroll
            for (int j = 0; j < 5; ++j) {
                const int i4 = lane + 32 * j;
                v[j] = x4[i4];
                ss = fmaf(v[j].x, v[j].x, ss);
                ss = fmaf(v[j].y, v[j].y, ss);
                ss = fmaf(v[j].z, v[j].z, ss);
                ss = fmaf(v[j].w, v[j].w, ss);
                *(__half2*)(o + i4 * 4)     = __floats2half2_rn(v[j].x, v[j].y);
                *(__half2*)(o + i4 * 4 + 2) = __floats2half2_rn(v[j].z, v[j].w);
            }
            #pragma unroll
            for (int of = 16; of > 0; of >>= 1)
                ss += __shfl_xor_sync(0xffffffffu, ss, of);
            if (lane == 0) g_qnorm[row] = sqrtf(ss);
        } else {
            // ---- r row: normalize + fp16 (or zero pad) ----
            const int r = row - MQ;
            __half* o = g_rh + (size_t)r * D_;
            if (r >= NR) {
                #pragma unroll
                for (int j = 0; j < 5; ++j) {
                    const int i4 = lane + 32 * j;
                    *(__half2*)(o + i4 * 4)     = __floats2half2_rn(0.f, 0.f);
                    *(__half2*)(o + i4 * 4 + 2) = __floats2half2_rn(0.f, 0.f);
                }
            } else {
                const float4* x4 = (const float4*)(r_patch + (size_t)r * D_);
                float4 v[5];
                float ss = 0.f;
                #pragma unroll
                for (int j = 0; j < 5; ++j) {
                    v[j] = x4[lane + 32 * j];
                    ss = fmaf(v[j].x, v[j].x, ss);
                    ss = fmaf(v[j].y, v[j].y, ss);
                    ss = fmaf(v[j].z, v[j].z, ss);
                    ss = fmaf(v[j].w, v[j].w, ss);
                }
                #pragma unroll
                for (int of = 16; of > 0; of >>= 1)
                    ss += __shfl_xor_sync(0xffffffffu, ss, of);
                const float sc = 1.f / (sqrtf(ss) + 1e-6f);
                #pragma unroll
                for (int j = 0; j < 5; ++j) {
                    const int i4 = lane + 32 * j;
                    *(__half2*)(o + i4 * 4) =
                        __floats2half2_rn(v[j].x * sc, v[j].y * sc);
                    *(__half2*)(o + i4 * 4 + 2) =
                        __floats2half2_rn(v[j].z * sc, v[j].w * sc);
                }
            }
        }
    } else {
        // ---- adapter hidden partials: 4 (k,dc) pairs per block ----
        const int grp = t >> 7;           // 0..3
        const int tg = t & 127;
        const int idx = (blockIdx.x - ROWBLKS) * 4 + grp;   // 0..79
        const int k = idx / 5, dc = idx % 5;
        __shared__ float axr[4][128];
        axr[grp][tg] = r_img[k * D_ + dc * 128 + tg];
        __syncthreads();
        const float* xr = axr[grp];
        #pragma unroll
        for (int rep = 0; rep < 2; ++rep) {
            const int i = tg + rep * 128;
            if (i < 160) {
                float s0 = 0.f, s1 = 0.f;
                const float* w = w1 + (size_t)(dc * 128) * 160 + i;
                #pragma unroll 8
                for (int d = 0; d < 128; d += 2) {
                    s0 = fmaf(xr[d], w[(size_t)d * 160], s0);
                    s1 = fmaf(xr[d + 1], w[(size_t)(d + 1) * 160], s1);
                }
                g_h1p[dc][k * 160 + i] = s0 + s1;
            }
        }
    }
}

// ---------------------------------------------------------------------------
// Kernel 2: adapter finish — combine partials + relu, then second layer
// ---------------------------------------------------------------------------
__global__ void adapter_final_kernel(const float* __restrict__ w2) {
    __shared__ float h1s[K_ * 160];
    for (int idx = threadIdx.x; idx < K_ * 160; idx += 128) {
        float s = g_h1p[0][idx] + g_h1p[1][idx] + g_h1p[2][idx] +
                  g_h1p[3][idx] + g_h1p[4][idx];
        h1s[idx] = fmaxf(s, 0.f);
    }
    __syncthreads();
    const int j = blockIdx.x * 128 + threadIdx.x;
    float accm = 0.f;
    for (int k = 0; k < K_; ++k) {
        float s0 = 0.f, s1 = 0.f;
        const float* h = h1s + k * 160;
        #pragma unroll 4
        for (int i = 0; i < 160; i += 2) {
            s0 = fmaf(h[i], w2[i * D_ + j], s0);
            s1 = fmaf(h[i + 1], w2[(i + 1) * D_ + j], s1);
        }
        accm += fmaxf(s0 + s1, 0.f);
    }
    g_famean[j] = accm * (1.f / (float)K_);
}

// ---------------------------------------------------------------------------
// Kernel 3: tensor-core GEMM + row max. fp16 in, fp32 acc, ldmatrix operands.
// (unchanged from R9 — at mma.sync instruction-rate floor)
// ---------------------------------------------------------------------------
__global__ __launch_bounds__(256, 2)
void gemm_max_kernel() {
    extern __shared__ __align__(16) char smem[];
    __half* As = (__half*)smem;
    __half* Bs = (__half*)(smem + A_SMEM_BYTES);
    float* red = (float*)(smem + RED_OFF);

    const int tid  = threadIdx.x;
    const int lane = tid & 31;
    const int g    = lane >> 2;
    const int tig  = lane & 3;
    const int w    = tid >> 5;
    const int wy   = w >> 2;
    const int wx   = w & 3;
    const int rowBase = blockIdx.x * BM;
    const int by = blockIdx.y;

    {
        const __half* gq = g_qh + (size_t)rowBase * D_;
        #pragma unroll
        for (int i = 0; i < 20; ++i) {
            int idx = tid + i * 256;
            int row = idx / 80, kg = idx % 80;
            *(uint4*)(As + row * LDA + kg * 8) =
                *(const uint4*)(gq + (size_t)row * D_ + kg * 8);
        }
    }

    const uint32_t sbA = smem_u32(As);
    const uint32_t bsBase = smem_u32(Bs);

    const int aRow = (lane & 7) + ((lane >> 3) & 1) * 8;
    const int aCol = (lane >> 4) * 8;
    uint32_t aAddr[2];
    #pragma unroll
    for (int i = 0; i < 2; ++i)
        aAddr[i] = sbA +
            (uint32_t)(((wy * 32 + i * 16 + aRow) * LDA + aCol) * 2);
    const int bRow = lane & 7;
    const int bCol = ((lane >> 3) & 1) * 8;
    uint32_t bAddr[2];
    #pragma unroll
    for (int j = 0; j < 2; ++j)
        bAddr[j] = bsBase +
            (uint32_t)(((wx * 16 + j * 8 + bRow) * LDB + bCol) * 2);

    const int n0 = tid >> 3, kg0 = tid & 7;
    const int n1 = n0 + 32;

    const int ntiles = (NT_ - by + NSTRIPE - 1) / NSTRIPE;
    const int U = ntiles * 10;

    {
        const __half* s0 = g_rh + ((size_t)(by * BN) + n0) * D_ + kg0 * 8;
        const __half* s1 = g_rh + ((size_t)(by * BN) + n1) * D_ + kg0 * 8;
        cp_async16(bsBase + (uint32_t)(n0 * LDB + kg0 * 8) * 2, s0);
        cp_async16(bsBase + (uint32_t)(n1 * LDB + kg0 * 8) * 2, s1);
        CP_COMMIT();
    }
    CP_WAIT0();
    __syncthreads();

    float rm[2][2] = {{-1e30f, -1e30f}, {-1e30f, -1e30f}};
    float acc[2][2][4];

    int nt = by, kt = 0;
    for (int u = 0; u < U; ++u) {
        int kt1 = kt + 1, nt1 = nt;
        if (kt1 == 10) { kt1 = 0; nt1 = nt + NSTRIPE; }
        if (u + 1 < U) {
            const __half* s0 =
                g_rh + ((size_t)(nt1 * BN) + n0) * D_ + kt1 * BK + kg0 * 8;
            const __half* s1 =
                g_rh + ((size_t)(nt1 * BN) + n1) * D_ + kt1 * BK + kg0 * 8;
            const uint32_t dstb = bsBase + (uint32_t)(((u + 1) & 1) * BN * LDB) * 2;
            cp_async16(dstb + (uint32_t)(n0 * LDB + kg0 * 8) * 2, s0);
            cp_async16(dstb + (uint32_t)(n1 * LDB + kg0 * 8) * 2, s1);
            CP_COMMIT();
        }

        if (kt == 0) {
            #pragma unroll
            for (int i = 0; i < 2; ++i)
                #pragma unroll
                for (int j = 0; j < 2; ++j)
                    #pragma unroll
                    for (int r = 0; r < 4; ++r) acc[i][j][r] = 0.f;
        }

        const uint32_t bufOff = (uint32_t)((u & 1) * BN * LDB) * 2;
        const int kA0 = kt * BK;
        #pragma unroll
        for (int ks = 0; ks < 4; ++ks) {
            const uint32_t kOffA = (uint32_t)(kA0 + ks * 16) * 2;
            const uint32_t kOffB = bufOff + (uint32_t)(ks * 16) * 2;
            uint32_t a[2][4], b[2][2];
            ldsm_x4(a[0], aAddr[0] + kOffA);
            ldsm_x4(a[1], aAddr[1] + kOffA);
            ldsm_x2(b[0], bAddr[0] + kOffB);
            ldsm_x2(b[1], bAddr[1] + kOffB);
            #pragma unroll
            for (int i = 0; i < 2; ++i)
                #pragma unroll
                for (int j = 0; j < 2; ++j)
                    mma16816(acc[i][j], a[i], b[j]);
        }

        if (kt == 9) {
            const int nBase = nt * BN;
            #pragma unroll
            for (int j = 0; j < 2; ++j) {
                const int c0 = nBase + wx * 16 + j * 8 + tig * 2;
                const bool v0 = (c0 < NR), v1 = (c0 + 1 < NR);
                #pragma unroll
                for (int i = 0; i < 2; ++i) {
                    if (v0) {
                        rm[i][0] = fmaxf(rm[i][0], acc[i][j][0]);
                        rm[i][1] = fmaxf(rm[i][1], acc[i][j][2]);
                    }
                    if (v1) {
                        rm[i][0] = fmaxf(rm[i][0], acc[i][j][1]);
                        rm[i][1] = fmaxf(rm[i][1], acc[i][j][3]);
                    }
                }
            }
        }

        if (u + 1 < U) {
            CP_WAIT0();
            __syncthreads();
        }
        kt = kt1; nt = nt1;
    }

    #pragma unroll
    for (int i = 0; i < 2; ++i)
        #pragma unroll
        for (int s = 0; s < 2; ++s) {
            float v = rm[i][s];
            v = fmaxf(v, __shfl_xor_sync(0xffffffffu, v, 1));
            v = fmaxf(v, __shfl_xor_sync(0xffffffffu, v, 2));
            rm[i][s] = v;
        }
    __syncthreads();
    if (tig == 0) {
        #pragma unroll
        for (int i = 0; i < 2; ++i)
            #pragma unroll
            for (int s = 0; s < 2; ++s) {
                int row = wy * 32 + i * 16 + s * 8 + g;
                red[row * 5 + wx] = rm[i][s];
            }
    }
    __syncthreads();
    if (tid < BM) {
        float m = red[tid * 5 + 0];
        m = fmaxf(m, red[tid * 5 + 1]);
        m = fmaxf(m, red[tid * 5 + 2]);
        m = fmaxf(m, red[tid * 5 + 3]);
        g_pmax[by * MQ + rowBase + tid] = m;
    }
}

// ---------------------------------------------------------------------------
// Kernel 4: both heads + score; 512 threads, dr/dh paths run CONCURRENTLY.
// ---------------------------------------------------------------------------
__global__ __launch_bounds__(512)
void heads_kernel(
    const float* __restrict__ q_img,
    const float* __restrict__ dh_w1, const float* __restrict__ dh_b1,
    const float* __restrict__ dh_g2, const float* __restrict__ dh_be2,
    const float* __restrict__ dh_w2, const float* __restrict__ dh_b2,
    const float* __restrict__ dh_g3, const float* __restrict__ dh_be3,
    const float* __restrict__ dh_w3, const float* __restrict__ dh_b3,
    const float* __restrict__ dr_w1, const float* __restrict__ dr_b1,
    const float* __restrict__ dr_g2, const float* __restrict__ dr_be2,
    const float* __restrict__ dr_w2, const float* __restrict__ dr_b2,
    const float* __restrict__ dr_g3, const float* __restrict__ dr_be3,
    const float* __restrict__ dr_w3, const float* __restrict__ dr_b3,
    float* __restrict__ out) {
    const int b = blockIdx.x;
    const int t = threadIdx.x;          // 512 threads
    __shared__ float xr[D_];
    __shared__ float am[P_ + 3];
    __shared__ float partR[256], partH[256];
    __shared__ float h1r[128], h1h[128];
    __shared__ float h2r[64], h2h[64];
    __shared__ float s_ref_s, s_map_s, mean_s;

    for (int i = t; i < D_; i += 512) xr[i] = q_img[b * D_ + i] - g_famean[i];
    if (t < P_) {
        const int r = b * P_ + t;
        float mx = g_pmax[r];
        mx = fmaxf(mx, g_pmax[MQ + r]);
        mx = fmaxf(mx, g_pmax[2 * MQ + r]);
        mx = fmaxf(mx, g_pmax[3 * MQ + r]);
        am[t] = 0.5f * (1.f - mx / (g_qnorm[r] + 1e-6f));
    }
    __syncthreads();

    // ===== Phase 1: L1 for both heads in parallel =====
    if (t < 256) {
        // dr L1: 640 -> 128 (d-split x2, 4 accumulators)
        const int t2 = t & 127, half = t >> 7;
        const float* wp = dr_w1 + t2;
        const int d0 = half * 320;
        float s0 = 0.f, s1 = 0.f, s2 = 0.f, s3 = 0.f;
        #pragma unroll 4
        for (int d = 0; d < 320; d += 4) {
            s0 = fmaf(xr[d0 + d + 0], wp[(size_t)(d0 + d + 0) * 128], s0);
            s1 = fmaf(xr[d0 + d + 1], wp[(size_t)(d0 + d + 1) * 128], s1);
            s2 = fmaf(xr[d0 + d + 2], wp[(size_t)(d0 + d + 2) * 128], s2);
            s3 = fmaf(xr[d0 + d + 3], wp[(size_t)(d0 + d + 3) * 128], s3);
        }
        partR[t] = (s0 + s1) + (s2 + s3);
    } else {
        // dh L1: 225 -> 128 (p-split x2, 4 accumulators, static bounds)
        const int tt = t - 256;
        const int t2 = tt & 127, half = tt >> 7;
        const float* wp = dh_w1 + t2;
        const int p0 = half * 112;
        float s0 = 0.f, s1 = 0.f, s2 = 0.f, s3 = 0.f;
        #pragma unroll 4
        for (int k = 0; k < 112; k += 4) {
            s0 = fmaf(am[p0 + k + 0], wp[(size_t)(p0 + k + 0) * 128], s0);
            s1 = fmaf(am[p0 + k + 1], wp[(size_t)(p0 + k + 1) * 128], s1);
            s2 = fmaf(am[p0 + k + 2], wp[(size_t)(p0 + k + 2) * 128], s2);
            s3 = fmaf(am[p0 + k + 3], wp[(size_t)(p0 + k + 3) * 128], s3);
        }
        if (half) s0 = fmaf(am[224], wp[(size_t)224 * 128], s0);
        partH[tt] = (s0 + s1) + (s2 + s3);
    }
    __syncthreads();

    if (t < 128)
        h1r[t] = fmaxf(partR[t] + partR[t + 128] + dr_b1[t], 0.f)
                     * dr_g2[t] + dr_be2[t];
    else if (t < 256) {
        const int i = t - 128;
        h1h[i] = fmaxf(partH[i] + partH[i + 128] + dh_b1[i], 0.f)
                     * dh_g2[i] + dh_be2[i];
    }
    __syncthreads();

    // ===== Phase 2: L2 for both heads in parallel =====
    if (t < 128) {
        const int t2 = t & 63, half = t >> 6;
        const float* wp = dr_w2 + t2;
        const int i0 = half * 64;
        float s0 = 0.f, s1 = 0.f;
        #pragma unroll 8
        for (int i = 0; i < 64; i += 2) {
            s0 = fmaf(h1r[i0 + i], wp[(size_t)(i0 + i) * 64], s0);
            s1 = fmaf(h1r[i0 + i + 1], wp[(size_t)(i0 + i + 1) * 64], s1);
        }
        partR[t] = s0 + s1;
    } else if (t < 256) {
        const int tt = t - 128;
        const int t2 = tt & 63, half = tt >> 6;
        const float* wp = dh_w2 + t2;
        const int i0 = half * 64;
        float s0 = 0.f, s1 = 0.f;
        #pragma unroll 8
        for (int i = 0; i < 64; i += 2) {
            s0 = fmaf(h1h[i0 + i], wp[(size_t)(i0 + i) * 64], s0);
            s1 = fmaf(h1h[i0 + i + 1], wp[(size_t)(i0 + i + 1) * 64], s1);
        }
        partH[tt] = s0 + s1;
    }
    __syncthreads();

    if (t < 64)
        h2r[t] = fmaxf(partR[t] + partR[t + 64] + dr_b2[t], 0.f)
                     * dr_g3[t] + dr_be3[t];
    else if (t < 128) {
        const int i = t - 64;
        h2h[i] = fmaxf(partH[i] + partH[i + 64] + dh_b2[i], 0.f)
                     * dh_g3[i] + dh_be3[i];
    }
    __syncthreads();

    // ===== Phase 3: final dots + amap mean in 3 parallel warps =====
    const int wid = t >> 5, lane = t & 31;
    if (wid == 0) {
        float s = h2r[lane] * dr_w3[lane] + h2r[lane + 32] * dr_w3[lane + 32];
        #pragma unroll
        for (int o = 16; o > 0; o >>= 1) s += __shfl_xor_sync(0xffffffffu, s, o);
        if (lane == 0) s_ref_s = 1.f / (1.f + expf(-(s + dr_b3[0])));
    } else if (wid == 1) {
        float s = h2h[lane] * dh_w3[lane] + h2h[lane + 32] * dh_w3[lane + 32];
        #pragma unroll
        for (int o = 16; o > 0; o >>= 1) s += __shfl_xor_sync(0xffffffffu, s, o);
        if (lane == 0) s_map_s = 1.f / (1.f + expf(-(s + dh_b3[0])));
    } else if (wid == 2) {
        float s = 0.f;
        #pragma unroll
        for (int j = 0; j < 7; ++j) s += am[lane + 32 * j];
        if (lane == 0) s += am[224];
        #pragma unroll
        for (int o = 16; o > 0; o >>= 1) s += __shfl_xor_sync(0xffffffffu, s, o);
        if (lane == 0) mean_s = s * (1.f / (float)P_);
    }
    __syncthreads();
    if (t == 0) out[b] = 0.5f * (s_ref_s + s_map_s) + mean_s;
}

// ---------------------------------------------------------------------------
// Launch
// ---------------------------------------------------------------------------
extern "C" void kernel_launch(void* const* d_in, const int* in_sizes, int n_in,
                              void* d_out, int out_size) {
    const float* q_patch = (const float*)d_in[0];
    const float* r_patch = (const float*)d_in[1];
    const float* q_img   = (const float*)d_in[2];
    const float* r_img   = (const float*)d_in[3];
    const float* adpt_w1 = (const float*)d_in[4];
    const float* adpt_w2 = (const float*)d_in[5];
    const float* dh_w1  = (const float*)d_in[6];
    const float* dh_b1  = (const float*)d_in[7];
    const float* dh_g2  = (const float*)d_in[8];
    const float* dh_be2 = (const float*)d_in[9];
    const float* dh_w2  = (const float*)d_in[10];
    const float* dh_b2  = (const float*)d_in[11];
    const float* dh_g3  = (const float*)d_in[12];
    const float* dh_be3 = (const float*)d_in[13];
    const float* dh_w3  = (const float*)d_in[14];
    const float* dh_b3  = (const float*)d_in[15];
    const float* dr_w1  = (const float*)d_in[16];
    const float* dr_b1  = (const float*)d_in[17];
    const float* dr_g2  = (const float*)d_in[18];
    const float* dr_be2 = (const float*)d_in[19];
    const float* dr_w2  = (const float*)d_in[20];
    const float* dr_b2  = (const float*)d_in[21];
    const float* dr_g3  = (const float*)d_in[22];
    const float* dr_be3 = (const float*)d_in[23];
    const float* dr_w3  = (const float*)d_in[24];
    const float* dr_b3  = (const float*)d_in[25];
    float* out = (float*)d_out;

    static bool attr_set = false;
    if (!attr_set) {
        cudaFuncSetAttribute(gemm_max_kernel,
                             cudaFuncAttributeMaxDynamicSharedMemorySize,
                             SMEM_BYTES);
        attr_set = true;
    }

    mega_prep_kernel<<<PREP_BLOCKS, 512>>>(q_patch, r_patch, r_img, adpt_w1);
    adapter_final_kernel<<<D_ / 128, 128>>>(adpt_w2);
    gemm_max_kernel<<<dim3(MQ / BM, NSTRIPE), 256, SMEM_BYTES>>>();
    heads_kernel<<<B_, 512>>>(q_img,
                              dh_w1, dh_b1, dh_g2, dh_be2, dh_w2, dh_b2,
                              dh_g3, dh_be3, dh_w3, dh_b3,
                              dr_w1, dr_b1, dr_g2, dr_be2, dr_w2, dr_b2,
                              dr_g3, dr_be3, dr_w3, dr_b3,
                              out);
}

// round 11
// speedup vs baseline: 1.2027x; 1.0105x over previous
#include <cuda_runtime.h>
#include <cuda_fp16.h>
#include <math.h>
#include <stdint.h>

// ---------------------------------------------------------------------------
// Problem constants
// ---------------------------------------------------------------------------
#define B_   64
#define P_   225
#define K_   16
#define D_   640
#define MQ   (B_ * P_)      // 14400 query rows
#define NR   (K_ * P_)      // 3600 reference rows
#define NRP  3648           // NR padded to 57*64
#define NT_  57             // n tiles of 64

// GEMM tiling
#define BM 64
#define BN 64
#define BK 64
#define LDA 648             // A smem row stride (fp16), row stride = 4 banks
#define LDB 72              // B smem row stride (144B), row stride = 4 banks
#define NSTRIPE 4
#define NSTAGE 3

#define A_SMEM_BYTES (BM * LDA * 2)                 // 82944
#define B_SMEM_BYTES (NSTAGE * BN * LDB * 2)        // 27648
#define RED_OFF      (A_SMEM_BYTES + B_SMEM_BYTES)  // 110592
#define SMEM_BYTES   (RED_OFF + BM * 5 * 4)         // 111872

// prep: 16 rows per 512-thread block (warp per row) + adapter tail blocks
#define ROWBLKS ((MQ + NRP) / 16)                   // 1128
#define ADPT_BLKS 20                                // 80 (k,dc) pairs / 4
#define PREP_BLOCKS (ROWBLKS + ADPT_BLKS)           // 1148

// ---------------------------------------------------------------------------
// Scratch (allocation-free: __device__ globals)
// ---------------------------------------------------------------------------
__device__ __half g_qh[MQ * D_];            // raw q_patch in fp16
__device__ __half g_rh[NRP * D_];           // normalized r_patch fp16 (pad 0)
__device__ float g_qnorm[MQ];               // ||q_patch row||
__device__ float g_pmax[NSTRIPE * MQ];      // per-stripe max of q.rn
__device__ float g_h1p[5][K_ * 160];        // adapter partials
__device__ float g_famean[D_];              // mean adapter output

// ---------------------------------------------------------------------------
// helpers
// ---------------------------------------------------------------------------
__device__ __forceinline__ uint32_t smem_u32(const void* p) {
    uint32_t a;
    asm("{ .reg .u64 t; cvta.to.shared.u64 t, %1; cvt.u32.u64 %0, t; }"
        : "=r"(a) : "l"(p));
    return a;
}
__device__ __forceinline__ void cp_async16(uint32_t dst, const void* src) {
    asm volatile("cp.async.cg.shared.global [%0], [%1], 16;"
                 :: "r"(dst), "l"(src) : "memory");
}
#define CP_COMMIT() asm volatile("cp.async.commit_group;" ::: "memory")
#define CP_WAIT0()  asm volatile("cp.async.wait_group 0;" ::: "memory")
#define CP_WAIT1()  asm volatile("cp.async.wait_group 1;" ::: "memory")

__device__ __forceinline__ void ldsm_x4(uint32_t r[4], uint32_t addr) {
    asm volatile("ldmatrix.sync.aligned.m8n8.x4.shared.b16 {%0,%1,%2,%3}, [%4];"
                 : "=r"(r[0]), "=r"(r[1]), "=r"(r[2]), "=r"(r[3]) : "r"(addr));
}
__device__ __forceinline__ void ldsm_x2(uint32_t r[2], uint32_t addr) {
    asm volatile("ldmatrix.sync.aligned.m8n8.x2.shared.b16 {%0,%1}, [%2];"
                 : "=r"(r[0]), "=r"(r[1]) : "r"(addr));
}

// mma.sync fp16 inputs, fp32 accumulate
__device__ __forceinline__ void mma16816(float c[4], const uint32_t a[4],
                                         const uint32_t b[2]) {
    asm volatile(
        "mma.sync.aligned.m16n8k16.row.col.f32.f16.f16.f32 "
        "{%0,%1,%2,%3}, {%4,%5,%6,%7}, {%8,%9}, {%0,%1,%2,%3};\n"
        : "+f"(c[0]), "+f"(c[1]), "+f"(c[2]), "+f"(c[3])
        : "r"(a[0]), "r"(a[1]), "r"(a[2]), "r"(a[3]), "r"(b[0]), "r"(b[1]));
}

// ---------------------------------------------------------------------------
// Kernel 1 (fused prep): warp-per-row q/r prep + adapter hidden partials
// ---------------------------------------------------------------------------
__global__ __launch_bounds__(512)
void mega_prep_kernel(const float* __restrict__ q_patch,
                      const float* __restrict__ r_patch,
                      const float* __restrict__ r_img,
                      const float* __restrict__ w1) {
    const int t = threadIdx.x;

    if (blockIdx.x < ROWBLKS) {
        const int lane = t & 31;
        const int row = blockIdx.x * 16 + (t >> 5);
        if (row < MQ) {
            const float4* x4 = (const float4*)(q_patch + (size_t)row * D_);
            __half* o = g_qh + (size_t)row * D_;
            float4 v[5];
            float ss = 0.f;
            #pragma unroll
            for (int j = 0; j < 5; ++j) {
                const int i4 = lane + 32 * j;
                v[j] = x4[i4];
                ss = fmaf(v[j].x, v[j].x, ss);
                ss = fmaf(v[j].y, v[j].y, ss);
                ss = fmaf(v[j].z, v[j].z, ss);
                ss = fmaf(v[j].w, v[j].w, ss);
                *(__half2*)(o + i4 * 4)     = __floats2half2_rn(v[j].x, v[j].y);
                *(__half2*)(o + i4 * 4 + 2) = __floats2half2_rn(v[j].z, v[j].w);
            }
            #pragma unroll
            for (int of = 16; of > 0; of >>= 1)
                ss += __shfl_xor_sync(0xffffffffu, ss, of);
            if (lane == 0) g_qnorm[row] = sqrtf(ss);
        } else {
            const int r = row - MQ;
            __half* o = g_rh + (size_t)r * D_;
            if (r >= NR) {
                #pragma unroll
                for (int j = 0; j < 5; ++j) {
                    const int i4 = lane + 32 * j;
                    *(__half2*)(o + i4 * 4)     = __floats2half2_rn(0.f, 0.f);
                    *(__half2*)(o + i4 * 4 + 2) = __floats2half2_rn(0.f, 0.f);
                }
            } else {
                const float4* x4 = (const float4*)(r_patch + (size_t)r * D_);
                float4 v[5];
                float ss = 0.f;
                #pragma unroll
                for (int j = 0; j < 5; ++j) {
                    v[j] = x4[lane + 32 * j];
                    ss = fmaf(v[j].x, v[j].x, ss);
                    ss = fmaf(v[j].y, v[j].y, ss);
                    ss = fmaf(v[j].z, v[j].z, ss);
                    ss = fmaf(v[j].w, v[j].w, ss);
                }
                #pragma unroll
                for (int of = 16; of > 0; of >>= 1)
                    ss += __shfl_xor_sync(0xffffffffu, ss, of);
                const float sc = 1.f / (sqrtf(ss) + 1e-6f);
                #pragma unroll
                for (int j = 0; j < 5; ++j) {
                    const int i4 = lane + 32 * j;
                    *(__half2*)(o + i4 * 4) =
                        __floats2half2_rn(v[j].x * sc, v[j].y * sc);
                    *(__half2*)(o + i4 * 4 + 2) =
                        __floats2half2_rn(v[j].z * sc, v[j].w * sc);
                }
            }
        }
    } else {
        const int grp = t >> 7;           // 0..3
        const int tg = t & 127;
        const int idx = (blockIdx.x - ROWBLKS) * 4 + grp;   // 0..79
        const int k = idx / 5, dc = idx % 5;
        __shared__ float axr[4][128];
        axr[grp][tg] = r_img[k * D_ + dc * 128 + tg];
        __syncthreads();
        const float* xr = axr[grp];
        #pragma unroll
        for (int rep = 0; rep < 2; ++rep) {
            const int i = tg + rep * 128;
            if (i < 160) {
                float s0 = 0.f, s1 = 0.f;
                const float* w = w1 + (size_t)(dc * 128) * 160 + i;
                #pragma unroll 8
                for (int d = 0; d < 128; d += 2) {
                    s0 = fmaf(xr[d], w[(size_t)d * 160], s0);
                    s1 = fmaf(xr[d + 1], w[(size_t)(d + 1) * 160], s1);
                }
                g_h1p[dc][k * 160 + i] = s0 + s1;
            }
        }
    }
}

// ---------------------------------------------------------------------------
// Kernel 2: adapter finish — combine partials + relu, then second layer
// ---------------------------------------------------------------------------
__global__ void adapter_final_kernel(const float* __restrict__ w2) {
    __shared__ float h1s[K_ * 160];
    for (int idx = threadIdx.x; idx < K_ * 160; idx += 128) {
        float s = g_h1p[0][idx] + g_h1p[1][idx] + g_h1p[2][idx] +
                  g_h1p[3][idx] + g_h1p[4][idx];
        h1s[idx] = fmaxf(s, 0.f);
    }
    __syncthreads();
    const int j = blockIdx.x * 128 + threadIdx.x;
    float accm = 0.f;
    for (int k = 0; k < K_; ++k) {
        float s0 = 0.f, s1 = 0.f;
        const float* h = h1s + k * 160;
        #pragma unroll 4
        for (int i = 0; i < 160; i += 2) {
            s0 = fmaf(h[i], w2[i * D_ + j], s0);
            s1 = fmaf(h[i + 1], w2[(i + 1) * D_ + j], s1);
        }
        accm += fmaxf(s0 + s1, 0.f);
    }
    g_famean[j] = accm * (1.f / (float)K_);
}

// ---------------------------------------------------------------------------
// Kernel 3: tensor-core GEMM + row max. 3-stage cp.async pipeline.
// ---------------------------------------------------------------------------
__global__ __launch_bounds__(256, 2)
void gemm_max_kernel() {
    extern __shared__ __align__(16) char smem[];
    __half* As = (__half*)smem;
    __half* Bs = (__half*)(smem + A_SMEM_BYTES);
    float* red = (float*)(smem + RED_OFF);

    const int tid  = threadIdx.x;
    const int lane = tid & 31;
    const int g    = lane >> 2;
    const int tig  = lane & 3;
    const int w    = tid >> 5;
    const int wy   = w >> 2;
    const int wx   = w & 3;
    const int rowBase = blockIdx.x * BM;
    const int by = blockIdx.y;

    {
        const __half* gq = g_qh + (size_t)rowBase * D_;
        #pragma unroll
        for (int i = 0; i < 20; ++i) {
            int idx = tid + i * 256;
            int row = idx / 80, kg = idx % 80;
            *(uint4*)(As + row * LDA + kg * 8) =
                *(const uint4*)(gq + (size_t)row * D_ + kg * 8);
        }
    }

    const uint32_t sbA = smem_u32(As);
    const uint32_t bsBase = smem_u32(Bs);

    const int aRow = (lane & 7) + ((lane >> 3) & 1) * 8;
    const int aCol = (lane >> 4) * 8;
    uint32_t aAddr[2];
    #pragma unroll
    for (int i = 0; i < 2; ++i)
        aAddr[i] = sbA +
            (uint32_t)(((wy * 32 + i * 16 + aRow) * LDA + aCol) * 2);
    const int bRow = lane & 7;
    const int bCol = ((lane >> 3) & 1) * 8;
    uint32_t bAddr[2];
    #pragma unroll
    for (int j = 0; j < 2; ++j)
        bAddr[j] = bsBase +
            (uint32_t)(((wx * 16 + j * 8 + bRow) * LDB + bCol) * 2);

    const int n0 = tid >> 3, kg0 = tid & 7;
    const int n1 = n0 + 32;
    const uint32_t d0off = (uint32_t)(n0 * LDB + kg0 * 8) * 2;
    const uint32_t d1off = (uint32_t)(n1 * LDB + kg0 * 8) * 2;

    const int ntiles = (NT_ - by + NSTRIPE - 1) / NSTRIPE;
    const int U = ntiles * 10;    // >= 140

    // ---- prologue: chunks 0 (buf0) and 1 (buf1) ----
    {
        const __half* c0 = g_rh + ((size_t)(by * BN)) * D_ + kg0 * 8;
        cp_async16(bsBase + d0off, c0 + (size_t)n0 * D_);
        cp_async16(bsBase + d1off, c0 + (size_t)n1 * D_);
        CP_COMMIT();
        const __half* c1 = g_rh + ((size_t)(by * BN)) * D_ + BK + kg0 * 8;
        const uint32_t b1 = bsBase + (uint32_t)(BN * LDB) * 2;
        cp_async16(b1 + d0off, c1 + (size_t)n0 * D_);
        cp_async16(b1 + d1off, c1 + (size_t)n1 * D_);
        CP_COMMIT();
    }
    CP_WAIT1();       // chunk 0 landed
    __syncthreads();

    float rm[2][2] = {{-1e30f, -1e30f}, {-1e30f, -1e30f}};
    float acc[2][2][4];

    int nt = by, kt = 0;          // coords of chunk u
    int nt2 = by, kt2 = 2;        // coords of chunk u+2
    int bufc = 0;                 // buffer of chunk u

    for (int u = 0; u < U; ++u) {
        // issue copy of chunk u+2 into buffer (bufc+2)%3
        if (u + 2 < U) {
            int bi2 = bufc + 2; if (bi2 >= NSTAGE) bi2 -= NSTAGE;
            const __half* s =
                g_rh + ((size_t)(nt2 * BN)) * D_ + kt2 * BK + kg0 * 8;
            const uint32_t dstb = bsBase + (uint32_t)(bi2 * BN * LDB) * 2;
            cp_async16(dstb + d0off, s + (size_t)n0 * D_);
            cp_async16(dstb + d1off, s + (size_t)n1 * D_);
            CP_COMMIT();
        }

        if (kt == 0) {
            #pragma unroll
            for (int i = 0; i < 2; ++i)
                #pragma unroll
                for (int j = 0; j < 2; ++j)
                    #pragma unroll
                    for (int r = 0; r < 4; ++r) acc[i][j][r] = 0.f;
        }

        // ---- compute chunk u ----
        const uint32_t bufOff = (uint32_t)(bufc * BN * LDB) * 2;
        #pragma unroll
        for (int ks = 0; ks < 4; ++ks) {
            const uint32_t kOffA = (uint32_t)(kt * BK + ks * 16) * 2;
            const uint32_t kOffB = bufOff + (uint32_t)(ks * 16) * 2;
            uint32_t a[2][4], b[2][2];
            ldsm_x4(a[0], aAddr[0] + kOffA);
            ldsm_x4(a[1], aAddr[1] + kOffA);
            ldsm_x2(b[0], bAddr[0] + kOffB);
            ldsm_x2(b[1], bAddr[1] + kOffB);
            #pragma unroll
            for (int i = 0; i < 2; ++i)
                #pragma unroll
                for (int j = 0; j < 2; ++j)
                    mma16816(acc[i][j], a[i], b[j]);
        }

        if (kt == 9) {
            const int nBase = nt * BN;
            #pragma unroll
            for (int j = 0; j < 2; ++j) {
                const int c0 = nBase + wx * 16 + j * 8 + tig * 2;
                const bool v0 = (c0 < NR), v1 = (c0 + 1 < NR);
                #pragma unroll
                for (int i = 0; i < 2; ++i) {
                    if (v0) {
                        rm[i][0] = fmaxf(rm[i][0], acc[i][j][0]);
                        rm[i][1] = fmaxf(rm[i][1], acc[i][j][2]);
                    }
                    if (v1) {
                        rm[i][0] = fmaxf(rm[i][0], acc[i][j][1]);
                        rm[i][1] = fmaxf(rm[i][1], acc[i][j][3]);
                    }
                }
            }
        }

        if (u + 1 < U) {
            if (u + 2 < U) { CP_WAIT1(); }   // chunk u+1 landed, u+2 in flight
            else          { CP_WAIT0(); }
            __syncthreads();
        }
        // advance coords
        if (++kt == 10) { kt = 0; nt += NSTRIPE; }
        if (++kt2 == 10) { kt2 = 0; nt2 += NSTRIPE; }
        if (++bufc == NSTAGE) bufc = 0;
    }

    #pragma unroll
    for (int i = 0; i < 2; ++i)
        #pragma unroll
        for (int s = 0; s < 2; ++s) {
            float v = rm[i][s];
            v = fmaxf(v, __shfl_xor_sync(0xffffffffu, v, 1));
            v = fmaxf(v, __shfl_xor_sync(0xffffffffu, v, 2));
            rm[i][s] = v;
        }
    __syncthreads();
    if (tig == 0) {
        #pragma unroll
        for (int i = 0; i < 2; ++i)
            #pragma unroll
            for (int s = 0; s < 2; ++s) {
                int row = wy * 32 + i * 16 + s * 8 + g;
                red[row * 5 + wx] = rm[i][s];
            }
    }
    __syncthreads();
    if (tid < BM) {
        float m = red[tid * 5 + 0];
        m = fmaxf(m, red[tid * 5 + 1]);
        m = fmaxf(m, red[tid * 5 + 2]);
        m = fmaxf(m, red[tid * 5 + 3]);
        g_pmax[by * MQ + rowBase + tid] = m;
    }
}

// ---------------------------------------------------------------------------
// Kernel 4: both heads + score; 512 threads; float4 weight loads, wide MLP.
// ---------------------------------------------------------------------------
__global__ __launch_bounds__(512)
void heads_kernel(
    const float* __restrict__ q_img,
    const float* __restrict__ dh_w1, const float* __restrict__ dh_b1,
    const float* __restrict__ dh_g2, const float* __restrict__ dh_be2,
    const float* __restrict__ dh_w2, const float* __restrict__ dh_b2,
    const float* __restrict__ dh_g3, const float* __restrict__ dh_be3,
    const float* __restrict__ dh_w3, const float* __restrict__ dh_b3,
    const float* __restrict__ dr_w1, const float* __restrict__ dr_b1,
    const float* __restrict__ dr_g2, const float* __restrict__ dr_be2,
    const float* __restrict__ dr_w2, const float* __restrict__ dr_b2,
    const float* __restrict__ dr_g3, const float* __restrict__ dr_be3,
    const float* __restrict__ dr_w3, const float* __restrict__ dr_b3,
    float* __restrict__ out) {
    const int b = blockIdx.x;
    const int t = threadIdx.x;          // 512 threads
    __shared__ float xr[D_];
    __shared__ float am[P_ + 7];
    __shared__ float4 p1r[8 * 32];      // 8 splits x 32 neuron-groups
    __shared__ float4 p1h[8 * 32];
    __shared__ float p2r[256], p2h[256];
    __shared__ float h1r[128], h1h[128];
    __shared__ float h2r[64], h2h[64];
    __shared__ float s_ref_s, s_map_s, mean_s;

    for (int i = t; i < D_; i += 512) xr[i] = q_img[b * D_ + i] - g_famean[i];
    if (t < P_) {
        const int r = b * P_ + t;
        float mx = g_pmax[r];
        mx = fmaxf(mx, g_pmax[MQ + r]);
        mx = fmaxf(mx, g_pmax[2 * MQ + r]);
        mx = fmaxf(mx, g_pmax[3 * MQ + r]);
        am[t] = 0.5f * (1.f - mx / (g_qnorm[r] + 1e-6f));
    }
    __syncthreads();

    // ===== Phase 1: L1 for both heads, float4 weights =====
    if (t < 256) {
        // dr L1: neuron group ng (4 neurons), d-split s of 80
        const int ng = t & 31, s = t >> 5;
        const int d0 = s * 80;
        const float4* wp = (const float4*)dr_w1 + ng;
        float a0 = 0.f, a1 = 0.f, a2 = 0.f, a3 = 0.f;
        #pragma unroll 8
        for (int d = 0; d < 80; ++d) {
            const float xv = xr[d0 + d];
            const float4 wv = wp[(size_t)(d0 + d) * 32];
            a0 = fmaf(xv, wv.x, a0);
            a1 = fmaf(xv, wv.y, a1);
            a2 = fmaf(xv, wv.z, a2);
            a3 = fmaf(xv, wv.w, a3);
        }
        p1r[s * 32 + ng] = make_float4(a0, a1, a2, a3);
    } else {
        // dh L1: neuron group ng, p-split s of 29 (225 guard)
        const int tt = t - 256;
        const int ng = tt & 31, s = tt >> 5;
        const int p0 = s * 29;
        const float4* wp = (const float4*)dh_w1 + ng;
        float a0 = 0.f, a1 = 0.f, a2 = 0.f, a3 = 0.f;
        #pragma unroll
        for (int i = 0; i < 29; ++i) {
            const int p = p0 + i;
            if (p < P_) {
                const float av = am[p];
                const float4 wv = wp[(size_t)p * 32];
                a0 = fmaf(av, wv.x, a0);
                a1 = fmaf(av, wv.y, a1);
                a2 = fmaf(av, wv.z, a2);
                a3 = fmaf(av, wv.w, a3);
            }
        }
        p1h[s * 32 + ng] = make_float4(a0, a1, a2, a3);
    }
    __syncthreads();

    if (t < 128) {
        const float* p = (const float*)p1r;
        float s8 = p[t] + p[128 + t] + p[256 + t] + p[384 + t] +
                   p[512 + t] + p[640 + t] + p[768 + t] + p[896 + t];
        h1r[t] = fmaxf(s8 + dr_b1[t], 0.f) * dr_g2[t] + dr_be2[t];
    } else if (t < 256) {
        const int i = t - 128;
        const float* p = (const float*)p1h;
        float s8 = p[i] + p[128 + i] + p[256 + i] + p[384 + i] +
                   p[512 + i] + p[640 + i] + p[768 + i] + p[896 + i];
        h1h[i] = fmaxf(s8 + dh_b1[i], 0.f) * dh_g2[i] + dh_be2[i];
    }
    __syncthreads();

    // ===== Phase 2: L2 for both heads, i-split x4 =====
    if (t < 256) {
        const int t2 = t & 63, q = t >> 6;
        const int i0 = q * 32;
        const float* wp = dr_w2 + t2;
        float s0 = 0.f, s1 = 0.f;
        #pragma unroll 8
        for (int i = 0; i < 32; i += 2) {
            s0 = fmaf(h1r[i0 + i], wp[(size_t)(i0 + i) * 64], s0);
            s1 = fmaf(h1r[i0 + i + 1], wp[(size_t)(i0 + i + 1) * 64], s1);
        }
        p2r[t] = s0 + s1;
    } else {
        const int tt = t - 256;
        const int t2 = tt & 63, q = tt >> 6;
        const int i0 = q * 32;
        const float* wp = dh_w2 + t2;
        float s0 = 0.f, s1 = 0.f;
        #pragma unroll 8
        for (int i = 0; i < 32; i += 2) {
            s0 = fmaf(h1h[i0 + i], wp[(size_t)(i0 + i) * 64], s0);
            s1 = fmaf(h1h[i0 + i + 1], wp[(size_t)(i0 + i + 1) * 64], s1);
        }
        p2h[tt] = s0 + s1;
    }
    __syncthreads();

    if (t < 64)
        h2r[t] = fmaxf(p2r[t] + p2r[t + 64] + p2r[t + 128] + p2r[t + 192] +
                       dr_b2[t], 0.f) * dr_g3[t] + dr_be3[t];
    else if (t < 128) {
        const int i = t - 64;
        h2h[i] = fmaxf(p2h[i] + p2h[i + 64] + p2h[i + 128] + p2h[i + 192] +
                       dh_b2[i], 0.f) * dh_g3[i] + dh_be3[i];
    }
    __syncthreads();

    // ===== Phase 3: final dots + amap mean in 3 parallel warps =====
    const int wid = t >> 5, lane = t & 31;
    if (wid == 0) {
        float s = h2r[lane] * dr_w3[lane] + h2r[lane + 32] * dr_w3[lane + 32];
        #pragma unroll
        for (int o = 16; o > 0; o >>= 1) s += __shfl_xor_sync(0xffffffffu, s, o);
        if (lane == 0) s_ref_s = 1.f / (1.f + expf(-(s + dr_b3[0])));
    } else if (wid == 1) {
        float s = h2h[lane] * dh_w3[lane] + h2h[lane + 32] * dh_w3[lane + 32];
        #pragma unroll
        for (int o = 16; o > 0; o >>= 1) s += __shfl_xor_sync(0xffffffffu, s, o);
        if (lane == 0) s_map_s = 1.f / (1.f + expf(-(s + dh_b3[0])));
    } else if (wid == 2) {
        float s = 0.f;
        #pragma unroll
        for (int j = 0; j < 7; ++j) s += am[lane + 32 * j];
        if (lane == 0) s += am[224];
        #pragma unroll
        for (int o = 16; o > 0; o >>= 1) s += __shfl_xor_sync(0xffffffffu, s, o);
        if (lane == 0) mean_s = s * (1.f / (float)P_);
    }
    __syncthreads();
    if (t == 0) out[b] = 0.5f * (s_ref_s + s_map_s) + mean_s;
}

// ---------------------------------------------------------------------------
// Launch
// ---------------------------------------------------------------------------
extern "C" void kernel_launch(void* const* d_in, const int* in_sizes, int n_in,
                              void* d_out, int out_size) {
    const float* q_patch = (const float*)d_in[0];
    const float* r_patch = (const float*)d_in[1];
    const float* q_img   = (const float*)d_in[2];
    const float* r_img   = (const float*)d_in[3];
    const float* adpt_w1 = (const float*)d_in[4];
    const float* adpt_w2 = (const float*)d_in[5];
    const float* dh_w1  = (const float*)d_in[6];
    const float* dh_b1  = (const float*)d_in[7];
    const float* dh_g2  = (const float*)d_in[8];
    const float* dh_be2 = (const float*)d_in[9];
    const float* dh_w2  = (const float*)d_in[10];
    const float* dh_b2  = (const float*)d_in[11];
    const float* dh_g3  = (const float*)d_in[12];
    const float* dh_be3 = (const float*)d_in[13];
    const float* dh_w3  = (const float*)d_in[14];
    const float* dh_b3  = (const float*)d_in[15];
    const float* dr_w1  = (const float*)d_in[16];
    const float* dr_b1  = (const float*)d_in[17];
    const float* dr_g2  = (const float*)d_in[18];
    const float* dr_be2 = (const float*)d_in[19];
    const float* dr_w2  = (const float*)d_in[20];
    const float* dr_b2  = (const float*)d_in[21];
    const float* dr_g3  = (const float*)d_in[22];
    const float* dr_be3 = (const float*)d_in[23];
    const float* dr_w3  = (const float*)d_in[24];
    const float* dr_b3  = (const float*)d_in[25];
    float* out = (float*)d_out;

    static bool attr_set = false;
    if (!attr_set) {
        cudaFuncSetAttribute(gemm_max_kernel,
                             cudaFuncAttributeMaxDynamicSharedMemorySize,
                             SMEM_BYTES);
        attr_set = true;
    }

    mega_prep_kernel<<<PREP_BLOCKS, 512>>>(q_patch, r_patch, r_img, adpt_w1);
    adapter_final_kernel<<<D_ / 128, 128>>>(adpt_w2);
    gemm_max_kernel<<<dim3(MQ / BM, NSTRIPE), 256, SMEM_BYTES>>>();
    heads_kernel<<<B_, 512>>>(q_img,
                              dh_w1, dh_b1, dh_g2, dh_be2, dh_w2, dh_b2,
                              dh_g3, dh_be3, dh_w3, dh_b3,
                              dr_w1, dr_b1, dr_g2, dr_be2, dr_w2, dr_b2,
                              dr_g3, dr_be3, dr_w3, dr_b3,
                              out);
}